// round 1
// baseline (speedup 1.0000x reference)
#include <cuda_runtime.h>
#include <math.h>

// Problem dims (fixed by the dataset)
#define BQ 32
#define TQ 1024
#define DQ 1024
#define SQ 128
#define HQ 4096
#define MQ (BQ * TQ)   // 32768

// ---------------------------------------------------------------------------
// Scratch (static __device__ arrays; no runtime allocation allowed)
// ---------------------------------------------------------------------------
__device__ float g_lnx[(size_t)MQ * DQ];    // 128 MB  LN1 output
__device__ float g_inj[(size_t)MQ * SQ];    //  16 MB  injection projections [b][t][s]
__device__ float g_hseq[(size_t)MQ * SQ];   //  16 MB  scan states          [b][t][s]
__device__ float g_x2[(size_t)MQ * DQ];     // 128 MB  post-state residual
__device__ float g_hbuf[(size_t)MQ * HQ];   // 512 MB  MLP hidden
__device__ float g_x3[(size_t)MQ * DQ];     // 128 MB  MLP output

// ---------------------------------------------------------------------------
// Packed f32x2 helpers (Blackwell: doubles fp32 FMA throughput)
// ---------------------------------------------------------------------------
__device__ __forceinline__ unsigned long long pk2(float lo, float hi) {
    unsigned long long r;
    asm("mov.b64 %0, {%1, %2};" : "=l"(r) : "r"(__float_as_uint(lo)), "r"(__float_as_uint(hi)));
    return r;
}
__device__ __forceinline__ void fma2(unsigned long long& d, unsigned long long a, unsigned long long b) {
    asm("fma.rn.f32x2 %0, %1, %2, %3;" : "=l"(d) : "l"(a), "l"(b), "l"(d));
}

// ---------------------------------------------------------------------------
// LayerNorm kernel: one block per row of 1024 floats (256 thr x float4)
// RESID=false: out = LN(x); RESID=true: out = x + LN(x)
// ---------------------------------------------------------------------------
__device__ __forceinline__ void block_reduce2(float& a, float& b) {
    #pragma unroll
    for (int o = 16; o > 0; o >>= 1) {
        a += __shfl_xor_sync(0xFFFFFFFFu, a, o);
        b += __shfl_xor_sync(0xFFFFFFFFu, b, o);
    }
    __shared__ float sa[8], sb[8];
    int w = threadIdx.x >> 5, l = threadIdx.x & 31;
    if (l == 0) { sa[w] = a; sb[w] = b; }
    __syncthreads();
    if (w == 0) {
        a = (l < 8) ? sa[l] : 0.f;
        b = (l < 8) ? sb[l] : 0.f;
        #pragma unroll
        for (int o = 4; o > 0; o >>= 1) {
            a += __shfl_xor_sync(0xFFFFFFFFu, a, o);
            b += __shfl_xor_sync(0xFFFFFFFFu, b, o);
        }
        if (l == 0) { sa[0] = a; sb[0] = b; }
    }
    __syncthreads();
    a = sa[0];
    b = sb[0];
}

template <bool RESID>
__global__ __launch_bounds__(256)
void ln_kernel(const float* __restrict__ x, const float* __restrict__ w,
               const float* __restrict__ bias, float* __restrict__ out) {
    size_t row = blockIdx.x;
    const float4* xr = reinterpret_cast<const float4*>(x + row * DQ);
    float4 v = xr[threadIdx.x];
    float s = v.x + v.y + v.z + v.w;
    float s2 = v.x * v.x + v.y * v.y + v.z * v.z + v.w * v.w;
    block_reduce2(s, s2);
    float mean = s * (1.0f / DQ);
    float var = s2 * (1.0f / DQ) - mean * mean;
    float rs = rsqrtf(var + 1e-5f);
    float4 wv = reinterpret_cast<const float4*>(w)[threadIdx.x];
    float4 bv = reinterpret_cast<const float4*>(bias)[threadIdx.x];
    float4 o;
    o.x = (v.x - mean) * rs * wv.x + bv.x;
    o.y = (v.y - mean) * rs * wv.y + bv.y;
    o.z = (v.z - mean) * rs * wv.z + bv.z;
    o.w = (v.w - mean) * rs * wv.w + bv.w;
    if (RESID) { o.x += v.x; o.y += v.y; o.z += v.z; o.w += v.w; }
    reinterpret_cast<float4*>(out + row * DQ)[threadIdx.x] = o;
}

// ---------------------------------------------------------------------------
// Sequential per-batch scan. 32 blocks (one per batch), 128 threads (one per s).
// gate_w / state_flow transposed in dyn SMEM (conflict-free reads).
// ---------------------------------------------------------------------------
__global__ __launch_bounds__(128)
void scan_kernel(const float* __restrict__ gate_w, const float* __restrict__ gate_b,
                 const float* __restrict__ state_flow, const float* __restrict__ inj,
                 float* __restrict__ hseq) {
    extern __shared__ float dynsm[];
    float* gwT = dynsm;            // [k][s] = gate_w[s][k]
    float* sfT = dynsm + SQ * SQ;  // [k][s] = state_flow[s][k]
    __shared__ float h[SQ];

    int s = threadIdx.x;
    int b = blockIdx.x;

    for (int idx = s; idx < SQ * SQ; idx += SQ) {
        int r = idx >> 7;      // row  (s-index of weight)
        int c = idx & 127;     // col  (k-index)
        gwT[c * SQ + r] = gate_w[idx];
        sfT[c * SQ + r] = state_flow[idx];
    }
    float gb = gate_b[s];
    h[s] = 0.0f;
    __syncthreads();

    const float* injb = inj + (size_t)b * TQ * SQ;
    float* hb = hseq + (size_t)b * TQ * SQ;

    for (int t = 0; t < TQ; ++t) {
        float injv = injb[(size_t)t * SQ + s];  // issued early, overlaps dot
        float accg = gb, accf = 0.0f;
        #pragma unroll 16
        for (int k = 0; k < SQ; ++k) {
            float hk = h[k];
            accg += hk * gwT[k * SQ + s];
            accf += hk * sfT[k * SQ + s];
        }
        float hold = h[s];
        float g = 1.0f / (1.0f + expf(-(accg + injv)));
        float hn = (1.0f - g) * hold + g * accf;
        __syncthreads();
        h[s] = hn;
        hb[(size_t)t * SQ + s] = hn;
        __syncthreads();
    }
}

// ---------------------------------------------------------------------------
// SGEMM: C[M,N] = A[M,K] @ W[N,K]^T  (+ epilogue)
// 128x128 block tile, BK=8, 8x8 microtile, 256 threads, double-buffered SMEM,
// inner product via packed fma.rn.f32x2.
// ---------------------------------------------------------------------------
#define GBM 128
#define GBN 128
#define GBK 8

enum { EPI_NONE = 0, EPI_ADD = 1, EPI_BIAS_GELU = 2, EPI_BIAS = 3 };

__device__ __forceinline__ float gelu_exact(float x) {
    return 0.5f * x * (1.0f + erff(x * 0.7071067811865476f));
}

template <int EPI>
__global__ __launch_bounds__(256)
void sgemm(const float* __restrict__ A, const float* __restrict__ W,
           const float* __restrict__ extra,   // bias[N] or addend[M,N]
           float* __restrict__ C, int M, int N, int K) {
    __shared__ float As[2][GBK][GBM];
    __shared__ float Bs[2][GBK][GBN];

    const int tid = threadIdx.x;
    const int mBase = blockIdx.y * GBM;
    const int nBase = blockIdx.x * GBN;

    const int lr = tid >> 1;         // 0..127 : row within tile
    const int lc = (tid & 1) * 4;    // 0 or 4 : k-offset of this float4

    const float* Ag = A + (size_t)(mBase + lr) * K + lc;
    const float* Wg = W + (size_t)(nBase + lr) * K + lc;

    {   // tile 0
        float4 a = *(const float4*)Ag;
        float4 w = *(const float4*)Wg;
        As[0][lc + 0][lr] = a.x; As[0][lc + 1][lr] = a.y;
        As[0][lc + 2][lr] = a.z; As[0][lc + 3][lr] = a.w;
        Bs[0][lc + 0][lr] = w.x; Bs[0][lc + 1][lr] = w.y;
        Bs[0][lc + 2][lr] = w.z; Bs[0][lc + 3][lr] = w.w;
    }
    __syncthreads();

    const int tx = tid & 15;   // n microtile
    const int ty = tid >> 4;   // m microtile

    unsigned long long acc[8][4];
    #pragma unroll
    for (int i = 0; i < 8; ++i)
        #pragma unroll
        for (int j = 0; j < 4; ++j) acc[i][j] = 0ull;  // {+0.f,+0.f}

    const int tiles = K / GBK;
    for (int t = 0; t < tiles; ++t) {
        const int cur = t & 1;
        float4 na, nw;
        const bool has = (t + 1 < tiles);
        if (has) {
            na = *(const float4*)(Ag + (size_t)(t + 1) * GBK);
            nw = *(const float4*)(Wg + (size_t)(t + 1) * GBK);
        }
        #pragma unroll
        for (int k = 0; k < GBK; ++k) {
            float4 a0 = *(const float4*)&As[cur][k][ty * 8];
            float4 a1 = *(const float4*)&As[cur][k][ty * 8 + 4];
            float4 b0 = *(const float4*)&Bs[cur][k][tx * 8];
            float4 b1 = *(const float4*)&Bs[cur][k][tx * 8 + 4];
            unsigned long long bb[4] = { pk2(b0.x, b0.y), pk2(b0.z, b0.w),
                                         pk2(b1.x, b1.y), pk2(b1.z, b1.w) };
            float av[8] = { a0.x, a0.y, a0.z, a0.w, a1.x, a1.y, a1.z, a1.w };
            #pragma unroll
            for (int i = 0; i < 8; ++i) {
                unsigned long long ad = pk2(av[i], av[i]);
                #pragma unroll
                for (int j = 0; j < 4; ++j) fma2(acc[i][j], ad, bb[j]);
            }
        }
        if (has) {
            const int nb = cur ^ 1;
            As[nb][lc + 0][lr] = na.x; As[nb][lc + 1][lr] = na.y;
            As[nb][lc + 2][lr] = na.z; As[nb][lc + 3][lr] = na.w;
            Bs[nb][lc + 0][lr] = nw.x; Bs[nb][lc + 1][lr] = nw.y;
            Bs[nb][lc + 2][lr] = nw.z; Bs[nb][lc + 3][lr] = nw.w;
        }
        __syncthreads();
    }

    // epilogue
    float be[8];
    if (EPI == EPI_BIAS || EPI == EPI_BIAS_GELU) {
        const float* br = extra + nBase + tx * 8;
        float4 e0 = *(const float4*)br;
        float4 e1 = *(const float4*)(br + 4);
        be[0] = e0.x; be[1] = e0.y; be[2] = e0.z; be[3] = e0.w;
        be[4] = e1.x; be[5] = e1.y; be[6] = e1.z; be[7] = e1.w;
    }

    #pragma unroll
    for (int i = 0; i < 8; ++i) {
        const int mrow = mBase + ty * 8 + i;
        float* crow = C + (size_t)mrow * N + nBase + tx * 8;
        float o[8];
        #pragma unroll
        for (int j = 0; j < 4; ++j) {
            union { unsigned long long u; float2 f; } uc;
            uc.u = acc[i][j];
            o[2 * j]     = uc.f.x;
            o[2 * j + 1] = uc.f.y;
        }
        if (EPI == EPI_ADD) {
            const float* ar = extra + (size_t)mrow * N + nBase + tx * 8;
            float4 e0 = *(const float4*)ar;
            float4 e1 = *(const float4*)(ar + 4);
            o[0] += e0.x; o[1] += e0.y; o[2] += e0.z; o[3] += e0.w;
            o[4] += e1.x; o[5] += e1.y; o[6] += e1.z; o[7] += e1.w;
        } else if (EPI == EPI_BIAS) {
            #pragma unroll
            for (int j = 0; j < 8; ++j) o[j] += be[j];
        } else if (EPI == EPI_BIAS_GELU) {
            #pragma unroll
            for (int j = 0; j < 8; ++j) o[j] = gelu_exact(o[j] + be[j]);
        }
        float4 s0 = { o[0], o[1], o[2], o[3] };
        float4 s1 = { o[4], o[5], o[6], o[7] };
        *(float4*)crow = s0;
        *(float4*)(crow + 4) = s1;
    }
}

// ---------------------------------------------------------------------------
// Launch
// ---------------------------------------------------------------------------
extern "C" void kernel_launch(void* const* d_in, const int* in_sizes, int n_in,
                              void* d_out, int out_size) {
    const float* x          = (const float*)d_in[0];
    const float* ln1_w      = (const float*)d_in[1];
    const float* ln1_b      = (const float*)d_in[2];
    const float* state_flow = (const float*)d_in[3];
    const float* injection  = (const float*)d_in[4];
    const float* readout    = (const float*)d_in[5];
    const float* gate_w     = (const float*)d_in[6];
    const float* gate_b     = (const float*)d_in[7];
    const float* w1         = (const float*)d_in[8];
    const float* b1         = (const float*)d_in[9];
    const float* w2         = (const float*)d_in[10];
    const float* b2         = (const float*)d_in[11];
    const float* ln2_w      = (const float*)d_in[12];
    const float* ln2_b      = (const float*)d_in[13];
    float* out = (float*)d_out;

    float *lnx, *inj, *hseq, *x2, *hbuf, *x3;
    cudaGetSymbolAddress((void**)&lnx,  g_lnx);
    cudaGetSymbolAddress((void**)&inj,  g_inj);
    cudaGetSymbolAddress((void**)&hseq, g_hseq);
    cudaGetSymbolAddress((void**)&x2,   g_x2);
    cudaGetSymbolAddress((void**)&hbuf, g_hbuf);
    cudaGetSymbolAddress((void**)&x3,   g_x3);

    const int scan_smem = 2 * SQ * SQ * (int)sizeof(float);  // 128 KB
    cudaFuncSetAttribute(scan_kernel, cudaFuncAttributeMaxDynamicSharedMemorySize, scan_smem);

    // 1) LN1
    ln_kernel<false><<<MQ, 256>>>(x, ln1_w, ln1_b, lnx);
    // 2) inj[b,t,s] = ln_x @ injection^T   (M=32768, N=128, K=1024)
    sgemm<EPI_NONE><<<dim3(SQ / GBN, MQ / GBM), 256>>>(lnx, injection, nullptr, inj, MQ, SQ, DQ);
    // 3) sequential scan per batch -> hseq[b,t,s]
    scan_kernel<<<BQ, SQ, scan_smem>>>(gate_w, gate_b, state_flow, inj, hseq);
    // 4) x2 = ln_x + hseq @ readout^T       (M=32768, N=1024, K=128)
    sgemm<EPI_ADD><<<dim3(DQ / GBN, MQ / GBM), 256>>>(hseq, readout, lnx, x2, MQ, DQ, SQ);
    // 5) hbuf = gelu(x2 @ w1^T + b1)        (M=32768, N=4096, K=1024)
    sgemm<EPI_BIAS_GELU><<<dim3(HQ / GBN, MQ / GBM), 256>>>(x2, w1, b1, hbuf, MQ, HQ, DQ);
    // 6) x3 = hbuf @ w2^T + b2              (M=32768, N=1024, K=4096)
    sgemm<EPI_BIAS><<<dim3(DQ / GBN, MQ / GBM), 256>>>(hbuf, w2, b2, x3, MQ, DQ, HQ);
    // 7) out = x3 + LN(x3)
    ln_kernel<true><<<MQ, 256>>>(x3, ln2_w, ln2_b, out);
}

// round 2
// speedup vs baseline: 1.0001x; 1.0001x over previous
#include <cuda_runtime.h>
#include <math.h>

// Problem dims (fixed by the dataset)
#define BQ 32
#define TQ 1024
#define DQ 1024
#define SQ 128
#define HQ 4096
#define MQ (BQ * TQ)   // 32768

// ---------------------------------------------------------------------------
// Scratch (static __device__ arrays; no runtime allocation allowed)
// ---------------------------------------------------------------------------
__device__ float g_lnx[(size_t)MQ * DQ];    // 128 MB  LN1 output
__device__ float g_inj[(size_t)MQ * SQ];    //  16 MB  injection projections [b][t][s]
__device__ float g_hseq[(size_t)MQ * SQ];   //  16 MB  scan states          [b][t][s]
__device__ float g_x2[(size_t)MQ * DQ];     // 128 MB  post-state residual
__device__ float g_hbuf[(size_t)MQ * HQ];   // 512 MB  MLP hidden
__device__ float g_x3[(size_t)MQ * DQ];     // 128 MB  MLP output

// ---------------------------------------------------------------------------
// Packed f32x2 helpers (Blackwell: doubles fp32 FMA throughput)
// ---------------------------------------------------------------------------
__device__ __forceinline__ unsigned long long pk2(float lo, float hi) {
    unsigned long long r;
    asm("mov.b64 %0, {%1, %2};" : "=l"(r) : "r"(__float_as_uint(lo)), "r"(__float_as_uint(hi)));
    return r;
}
__device__ __forceinline__ void fma2(unsigned long long& d, unsigned long long a, unsigned long long b) {
    asm("fma.rn.f32x2 %0, %1, %2, %3;" : "=l"(d) : "l"(a), "l"(b), "l"(d));
}

// ---------------------------------------------------------------------------
// LayerNorm kernel: one block per row of 1024 floats (256 thr x float4)
// RESID=false: out = LN(x); RESID=true: out = x + LN(x)
// ---------------------------------------------------------------------------
__device__ __forceinline__ void block_reduce2(float& a, float& b) {
    #pragma unroll
    for (int o = 16; o > 0; o >>= 1) {
        a += __shfl_xor_sync(0xFFFFFFFFu, a, o);
        b += __shfl_xor_sync(0xFFFFFFFFu, b, o);
    }
    __shared__ float sa[8], sb[8];
    int w = threadIdx.x >> 5, l = threadIdx.x & 31;
    if (l == 0) { sa[w] = a; sb[w] = b; }
    __syncthreads();
    if (w == 0) {
        a = (l < 8) ? sa[l] : 0.f;
        b = (l < 8) ? sb[l] : 0.f;
        #pragma unroll
        for (int o = 4; o > 0; o >>= 1) {
            a += __shfl_xor_sync(0xFFFFFFFFu, a, o);
            b += __shfl_xor_sync(0xFFFFFFFFu, b, o);
        }
        if (l == 0) { sa[0] = a; sb[0] = b; }
    }
    __syncthreads();
    a = sa[0];
    b = sb[0];
}

template <bool RESID>
__global__ __launch_bounds__(256)
void ln_kernel(const float* __restrict__ x, const float* __restrict__ w,
               const float* __restrict__ bias, float* __restrict__ out) {
    size_t row = blockIdx.x;
    const float4* xr = reinterpret_cast<const float4*>(x + row * DQ);
    float4 v = xr[threadIdx.x];
    float s = v.x + v.y + v.z + v.w;
    float s2 = v.x * v.x + v.y * v.y + v.z * v.z + v.w * v.w;
    block_reduce2(s, s2);
    float mean = s * (1.0f / DQ);
    float var = s2 * (1.0f / DQ) - mean * mean;
    float rs = rsqrtf(var + 1e-5f);
    float4 wv = reinterpret_cast<const float4*>(w)[threadIdx.x];
    float4 bv = reinterpret_cast<const float4*>(bias)[threadIdx.x];
    float4 o;
    o.x = (v.x - mean) * rs * wv.x + bv.x;
    o.y = (v.y - mean) * rs * wv.y + bv.y;
    o.z = (v.z - mean) * rs * wv.z + bv.z;
    o.w = (v.w - mean) * rs * wv.w + bv.w;
    if (RESID) { o.x += v.x; o.y += v.y; o.z += v.z; o.w += v.w; }
    reinterpret_cast<float4*>(out + row * DQ)[threadIdx.x] = o;
}

// ---------------------------------------------------------------------------
// Sequential per-batch scan. 32 blocks (one per batch), 128 threads (one per s).
// gate_w / state_flow transposed in dyn SMEM (conflict-free reads).
// ---------------------------------------------------------------------------
__global__ __launch_bounds__(128)
void scan_kernel(const float* __restrict__ gate_w, const float* __restrict__ gate_b,
                 const float* __restrict__ state_flow, const float* __restrict__ inj,
                 float* __restrict__ hseq) {
    extern __shared__ float dynsm[];
    float* gwT = dynsm;            // [k][s] = gate_w[s][k]
    float* sfT = dynsm + SQ * SQ;  // [k][s] = state_flow[s][k]
    __shared__ float h[SQ];

    int s = threadIdx.x;
    int b = blockIdx.x;

    for (int idx = s; idx < SQ * SQ; idx += SQ) {
        int r = idx >> 7;      // row  (s-index of weight)
        int c = idx & 127;     // col  (k-index)
        gwT[c * SQ + r] = gate_w[idx];
        sfT[c * SQ + r] = state_flow[idx];
    }
    float gb = gate_b[s];
    h[s] = 0.0f;
    __syncthreads();

    const float* injb = inj + (size_t)b * TQ * SQ;
    float* hb = hseq + (size_t)b * TQ * SQ;

    for (int t = 0; t < TQ; ++t) {
        float injv = injb[(size_t)t * SQ + s];  // issued early, overlaps dot
        float accg = gb, accf = 0.0f;
        #pragma unroll 16
        for (int k = 0; k < SQ; ++k) {
            float hk = h[k];
            accg += hk * gwT[k * SQ + s];
            accf += hk * sfT[k * SQ + s];
        }
        float hold = h[s];
        float g = 1.0f / (1.0f + expf(-(accg + injv)));
        float hn = (1.0f - g) * hold + g * accf;
        __syncthreads();
        h[s] = hn;
        hb[(size_t)t * SQ + s] = hn;
        __syncthreads();
    }
}

// ---------------------------------------------------------------------------
// SGEMM: C[M,N] = A[M,K] @ W[N,K]^T  (+ epilogue)
// 128x128 block tile, BK=8, 8x8 microtile, 256 threads, double-buffered SMEM,
// inner product via packed fma.rn.f32x2.
// ---------------------------------------------------------------------------
#define GBM 128
#define GBN 128
#define GBK 8

enum { EPI_NONE = 0, EPI_ADD = 1, EPI_BIAS_GELU = 2, EPI_BIAS = 3 };

__device__ __forceinline__ float gelu_exact(float x) {
    return 0.5f * x * (1.0f + erff(x * 0.7071067811865476f));
}

template <int EPI>
__global__ __launch_bounds__(256)
void sgemm(const float* __restrict__ A, const float* __restrict__ W,
           const float* __restrict__ extra,   // bias[N] or addend[M,N]
           float* __restrict__ C, int M, int N, int K) {
    __shared__ float As[2][GBK][GBM];
    __shared__ float Bs[2][GBK][GBN];

    const int tid = threadIdx.x;
    const int mBase = blockIdx.y * GBM;
    const int nBase = blockIdx.x * GBN;

    const int lr = tid >> 1;         // 0..127 : row within tile
    const int lc = (tid & 1) * 4;    // 0 or 4 : k-offset of this float4

    const float* Ag = A + (size_t)(mBase + lr) * K + lc;
    const float* Wg = W + (size_t)(nBase + lr) * K + lc;

    {   // tile 0
        float4 a = *(const float4*)Ag;
        float4 w = *(const float4*)Wg;
        As[0][lc + 0][lr] = a.x; As[0][lc + 1][lr] = a.y;
        As[0][lc + 2][lr] = a.z; As[0][lc + 3][lr] = a.w;
        Bs[0][lc + 0][lr] = w.x; Bs[0][lc + 1][lr] = w.y;
        Bs[0][lc + 2][lr] = w.z; Bs[0][lc + 3][lr] = w.w;
    }
    __syncthreads();

    const int tx = tid & 15;   // n microtile
    const int ty = tid >> 4;   // m microtile

    unsigned long long acc[8][4];
    #pragma unroll
    for (int i = 0; i < 8; ++i)
        #pragma unroll
        for (int j = 0; j < 4; ++j) acc[i][j] = 0ull;  // {+0.f,+0.f}

    const int tiles = K / GBK;
    for (int t = 0; t < tiles; ++t) {
        const int cur = t & 1;
        float4 na, nw;
        const bool has = (t + 1 < tiles);
        if (has) {
            na = *(const float4*)(Ag + (size_t)(t + 1) * GBK);
            nw = *(const float4*)(Wg + (size_t)(t + 1) * GBK);
        }
        #pragma unroll
        for (int k = 0; k < GBK; ++k) {
            float4 a0 = *(const float4*)&As[cur][k][ty * 8];
            float4 a1 = *(const float4*)&As[cur][k][ty * 8 + 4];
            float4 b0 = *(const float4*)&Bs[cur][k][tx * 8];
            float4 b1 = *(const float4*)&Bs[cur][k][tx * 8 + 4];
            unsigned long long bb[4] = { pk2(b0.x, b0.y), pk2(b0.z, b0.w),
                                         pk2(b1.x, b1.y), pk2(b1.z, b1.w) };
            float av[8] = { a0.x, a0.y, a0.z, a0.w, a1.x, a1.y, a1.z, a1.w };
            #pragma unroll
            for (int i = 0; i < 8; ++i) {
                unsigned long long ad = pk2(av[i], av[i]);
                #pragma unroll
                for (int j = 0; j < 4; ++j) fma2(acc[i][j], ad, bb[j]);
            }
        }
        if (has) {
            const int nb = cur ^ 1;
            As[nb][lc + 0][lr] = na.x; As[nb][lc + 1][lr] = na.y;
            As[nb][lc + 2][lr] = na.z; As[nb][lc + 3][lr] = na.w;
            Bs[nb][lc + 0][lr] = nw.x; Bs[nb][lc + 1][lr] = nw.y;
            Bs[nb][lc + 2][lr] = nw.z; Bs[nb][lc + 3][lr] = nw.w;
        }
        __syncthreads();
    }

    // epilogue
    float be[8];
    if (EPI == EPI_BIAS || EPI == EPI_BIAS_GELU) {
        const float* br = extra + nBase + tx * 8;
        float4 e0 = *(const float4*)br;
        float4 e1 = *(const float4*)(br + 4);
        be[0] = e0.x; be[1] = e0.y; be[2] = e0.z; be[3] = e0.w;
        be[4] = e1.x; be[5] = e1.y; be[6] = e1.z; be[7] = e1.w;
    }

    #pragma unroll
    for (int i = 0; i < 8; ++i) {
        const int mrow = mBase + ty * 8 + i;
        float* crow = C + (size_t)mrow * N + nBase + tx * 8;
        float o[8];
        #pragma unroll
        for (int j = 0; j < 4; ++j) {
            union { unsigned long long u; float2 f; } uc;
            uc.u = acc[i][j];
            o[2 * j]     = uc.f.x;
            o[2 * j + 1] = uc.f.y;
        }
        if (EPI == EPI_ADD) {
            const float* ar = extra + (size_t)mrow * N + nBase + tx * 8;
            float4 e0 = *(const float4*)ar;
            float4 e1 = *(const float4*)(ar + 4);
            o[0] += e0.x; o[1] += e0.y; o[2] += e0.z; o[3] += e0.w;
            o[4] += e1.x; o[5] += e1.y; o[6] += e1.z; o[7] += e1.w;
        } else if (EPI == EPI_BIAS) {
            #pragma unroll
            for (int j = 0; j < 8; ++j) o[j] += be[j];
        } else if (EPI == EPI_BIAS_GELU) {
            #pragma unroll
            for (int j = 0; j < 8; ++j) o[j] = gelu_exact(o[j] + be[j]);
        }
        float4 s0 = { o[0], o[1], o[2], o[3] };
        float4 s1 = { o[4], o[5], o[6], o[7] };
        *(float4*)crow = s0;
        *(float4*)(crow + 4) = s1;
    }
}

// ---------------------------------------------------------------------------
// Launch
// ---------------------------------------------------------------------------
extern "C" void kernel_launch(void* const* d_in, const int* in_sizes, int n_in,
                              void* d_out, int out_size) {
    const float* x          = (const float*)d_in[0];
    const float* ln1_w      = (const float*)d_in[1];
    const float* ln1_b      = (const float*)d_in[2];
    const float* state_flow = (const float*)d_in[3];
    const float* injection  = (const float*)d_in[4];
    const float* readout    = (const float*)d_in[5];
    const float* gate_w     = (const float*)d_in[6];
    const float* gate_b     = (const float*)d_in[7];
    const float* w1         = (const float*)d_in[8];
    const float* b1         = (const float*)d_in[9];
    const float* w2         = (const float*)d_in[10];
    const float* b2         = (const float*)d_in[11];
    const float* ln2_w      = (const float*)d_in[12];
    const float* ln2_b      = (const float*)d_in[13];
    float* out = (float*)d_out;

    float *lnx, *inj, *hseq, *x2, *hbuf, *x3;
    cudaGetSymbolAddress((void**)&lnx,  g_lnx);
    cudaGetSymbolAddress((void**)&inj,  g_inj);
    cudaGetSymbolAddress((void**)&hseq, g_hseq);
    cudaGetSymbolAddress((void**)&x2,   g_x2);
    cudaGetSymbolAddress((void**)&hbuf, g_hbuf);
    cudaGetSymbolAddress((void**)&x3,   g_x3);

    const int scan_smem = 2 * SQ * SQ * (int)sizeof(float);  // 128 KB
    cudaFuncSetAttribute(scan_kernel, cudaFuncAttributeMaxDynamicSharedMemorySize, scan_smem);

    // 1) LN1
    ln_kernel<false><<<MQ, 256>>>(x, ln1_w, ln1_b, lnx);
    // 2) inj[b,t,s] = ln_x @ injection^T   (M=32768, N=128, K=1024)
    sgemm<EPI_NONE><<<dim3(SQ / GBN, MQ / GBM), 256>>>(lnx, injection, nullptr, inj, MQ, SQ, DQ);
    // 3) sequential scan per batch -> hseq[b,t,s]
    scan_kernel<<<BQ, SQ, scan_smem>>>(gate_w, gate_b, state_flow, inj, hseq);
    // 4) x2 = ln_x + hseq @ readout^T       (M=32768, N=1024, K=128)
    sgemm<EPI_ADD><<<dim3(DQ / GBN, MQ / GBM), 256>>>(hseq, readout, lnx, x2, MQ, DQ, SQ);
    // 5) hbuf = gelu(x2 @ w1^T + b1)        (M=32768, N=4096, K=1024)
    sgemm<EPI_BIAS_GELU><<<dim3(HQ / GBN, MQ / GBM), 256>>>(x2, w1, b1, hbuf, MQ, HQ, DQ);
    // 6) x3 = hbuf @ w2^T + b2              (M=32768, N=1024, K=4096)
    sgemm<EPI_BIAS><<<dim3(DQ / GBN, MQ / GBM), 256>>>(hbuf, w2, b2, x3, MQ, DQ, HQ);
    // 7) out = x3 + LN(x3)
    ln_kernel<true><<<MQ, 256>>>(x3, ln2_w, ln2_b, out);
}

// round 4
// speedup vs baseline: 1.9910x; 1.9909x over previous
#include <cuda_runtime.h>
#include <cuda_bf16.h>
#include <math.h>
#include <stdint.h>

#define BQ 32
#define TQ 1024
#define DQ 1024
#define SQ 128
#define HQ 4096
#define MQ (BQ * TQ)

// ---- scratch (hi/lo bf16 buffers are plain row-major) ----
__device__ __align__(16) float         g_lnx[(size_t)MQ * DQ];
__device__ __align__(16) __nv_bfloat16 g_lnx_hi[(size_t)MQ * DQ];
__device__ __align__(16) __nv_bfloat16 g_lnx_lo[(size_t)MQ * DQ];
__device__ __align__(16) float         g_inj[(size_t)MQ * SQ];
__device__ __align__(16) __nv_bfloat16 g_h_hi[(size_t)MQ * SQ];
__device__ __align__(16) __nv_bfloat16 g_h_lo[(size_t)MQ * SQ];
__device__ __align__(16) __nv_bfloat16 g_x2_hi[(size_t)MQ * DQ];
__device__ __align__(16) __nv_bfloat16 g_x2_lo[(size_t)MQ * DQ];
__device__ __align__(16) __nv_bfloat16 g_hb_hi[(size_t)MQ * HQ];
__device__ __align__(16) __nv_bfloat16 g_hb_lo[(size_t)MQ * HQ];
__device__ __align__(16) float         g_x3[(size_t)MQ * DQ];
__device__ __align__(16) __nv_bfloat16 g_wi_hi[SQ * DQ], g_wi_lo[SQ * DQ];
__device__ __align__(16) __nv_bfloat16 g_ro_hi[DQ * SQ], g_ro_lo[DQ * SQ];
__device__ __align__(16) __nv_bfloat16 g_w1_hi[(size_t)HQ * DQ], g_w1_lo[(size_t)HQ * DQ];
__device__ __align__(16) __nv_bfloat16 g_w2_hi[(size_t)DQ * HQ], g_w2_lo[(size_t)DQ * HQ];

// ---- helpers ----
__device__ __forceinline__ uint32_t smem_u32(const void* p) {
    uint32_t a;
    asm("{ .reg .u64 t; cvta.to.shared.u64 t, %1; cvt.u32.u64 %0, t; }" : "=r"(a) : "l"(p));
    return a;
}
__device__ __forceinline__ void cpa16(uint32_t s, const void* g) {
    asm volatile("cp.async.ca.shared.global [%0], [%1], 16;" :: "r"(s), "l"(g) : "memory");
}
__device__ __forceinline__ void ldsm4(uint32_t& r0, uint32_t& r1, uint32_t& r2, uint32_t& r3, uint32_t a) {
    asm volatile("ldmatrix.sync.aligned.m8n8.x4.shared.b16 {%0,%1,%2,%3}, [%4];"
                 : "=r"(r0), "=r"(r1), "=r"(r2), "=r"(r3) : "r"(a));
}
__device__ __forceinline__ void mma16816(float* c, const uint32_t* a, const uint32_t* b) {
    asm volatile("mma.sync.aligned.m16n8k16.row.col.f32.bf16.bf16.f32 "
                 "{%0,%1,%2,%3}, {%4,%5,%6,%7}, {%8,%9}, {%0,%1,%2,%3};"
                 : "+f"(c[0]), "+f"(c[1]), "+f"(c[2]), "+f"(c[3])
                 : "r"(a[0]), "r"(a[1]), "r"(a[2]), "r"(a[3]), "r"(b[0]), "r"(b[1]));
}
__device__ __forceinline__ uint32_t pkbf2(float a, float b) {
    __nv_bfloat162 t = __floats2bfloat162_rn(a, b);
    return *reinterpret_cast<uint32_t*>(&t);
}
__device__ __forceinline__ float gelu_exact(float x) {
    return 0.5f * x * (1.0f + erff(x * 0.7071067811865476f));
}
__device__ __forceinline__ void split_store2(__nv_bfloat16* ohi, __nv_bfloat16* olo,
                                             size_t off, float v0, float v1) {
    __nv_bfloat16 h0 = __float2bfloat16(v0), h1 = __float2bfloat16(v1);
    float l0 = v0 - __bfloat162float(h0), l1 = v1 - __bfloat162float(h1);
    *reinterpret_cast<uint32_t*>(ohi + off) = pkbf2(__bfloat162float(h0), __bfloat162float(h1));
    *reinterpret_cast<uint32_t*>(olo + off) = pkbf2(l0, l1);
}

// ---- conversion: fp32 [R,K] -> row-major hi/lo bf16 ----
__global__ __launch_bounds__(256)
void conv_split(const float* __restrict__ in, __nv_bfloat16* __restrict__ hi,
                __nv_bfloat16* __restrict__ lo, int K) {
    size_t idx = ((size_t)blockIdx.x * blockDim.x + threadIdx.x) * 8;
    const float4* p = reinterpret_cast<const float4*>(in + idx);
    float4 a = p[0], b = p[1];
    float v[8] = { a.x, a.y, a.z, a.w, b.x, b.y, b.z, b.w };
    float hf[8], lf[8];
    #pragma unroll
    for (int i = 0; i < 8; ++i) {
        __nv_bfloat16 h = __float2bfloat16(v[i]);
        hf[i] = __bfloat162float(h);
        lf[i] = v[i] - hf[i];
    }
    uint4 H = { pkbf2(hf[0], hf[1]), pkbf2(hf[2], hf[3]), pkbf2(hf[4], hf[5]), pkbf2(hf[6], hf[7]) };
    uint4 L = { pkbf2(lf[0], lf[1]), pkbf2(lf[2], lf[3]), pkbf2(lf[4], lf[5]), pkbf2(lf[6], lf[7]) };
    *reinterpret_cast<uint4*>(hi + idx) = H;
    *reinterpret_cast<uint4*>(lo + idx) = L;
}

// ---- LayerNorm ----
__device__ __forceinline__ void block_reduce2(float& a, float& b) {
    #pragma unroll
    for (int o = 16; o > 0; o >>= 1) {
        a += __shfl_xor_sync(0xFFFFFFFFu, a, o);
        b += __shfl_xor_sync(0xFFFFFFFFu, b, o);
    }
    __shared__ float sa[8], sb[8];
    int w = threadIdx.x >> 5, l = threadIdx.x & 31;
    if (l == 0) { sa[w] = a; sb[w] = b; }
    __syncthreads();
    if (w == 0) {
        a = (l < 8) ? sa[l] : 0.f;
        b = (l < 8) ? sb[l] : 0.f;
        #pragma unroll
        for (int o = 4; o > 0; o >>= 1) {
            a += __shfl_xor_sync(0xFFFFFFFFu, a, o);
            b += __shfl_xor_sync(0xFFFFFFFFu, b, o);
        }
        if (l == 0) { sa[0] = a; sb[0] = b; }
    }
    __syncthreads();
    a = sa[0]; b = sb[0];
}

template <bool RESID, bool SPLIT>
__global__ __launch_bounds__(256)
void ln_kernel(const float* __restrict__ x, const float* __restrict__ w,
               const float* __restrict__ bias, float* __restrict__ out,
               __nv_bfloat16* __restrict__ ohi, __nv_bfloat16* __restrict__ olo) {
    size_t row = blockIdx.x;
    float4 v = reinterpret_cast<const float4*>(x + row * DQ)[threadIdx.x];
    float s = v.x + v.y + v.z + v.w;
    float s2 = v.x * v.x + v.y * v.y + v.z * v.z + v.w * v.w;
    block_reduce2(s, s2);
    float mean = s * (1.0f / DQ);
    float rs = rsqrtf(s2 * (1.0f / DQ) - mean * mean + 1e-5f);
    float4 wv = reinterpret_cast<const float4*>(w)[threadIdx.x];
    float4 bv = reinterpret_cast<const float4*>(bias)[threadIdx.x];
    float4 o;
    o.x = (v.x - mean) * rs * wv.x + bv.x;
    o.y = (v.y - mean) * rs * wv.y + bv.y;
    o.z = (v.z - mean) * rs * wv.z + bv.z;
    o.w = (v.w - mean) * rs * wv.w + bv.w;
    if (RESID) { o.x += v.x; o.y += v.y; o.z += v.z; o.w += v.w; }
    reinterpret_cast<float4*>(out + row * DQ)[threadIdx.x] = o;
    if (SPLIT) {
        size_t off = row * DQ + 4 * threadIdx.x;
        split_store2(ohi, olo, off, o.x, o.y);
        split_store2(ohi, olo, off + 2, o.z, o.w);
    }
}

// ---- sequential scan ----
__global__ __launch_bounds__(128)
void scan_kernel(const float* __restrict__ gate_w, const float* __restrict__ gate_b,
                 const float* __restrict__ state_flow, const float* __restrict__ inj,
                 __nv_bfloat16* __restrict__ hhi, __nv_bfloat16* __restrict__ hlo) {
    extern __shared__ float dynsm[];
    float* gwT = dynsm;
    float* sfT = dynsm + SQ * SQ;
    __shared__ float h[SQ];
    int s = threadIdx.x, b = blockIdx.x;
    for (int idx = s; idx < SQ * SQ; idx += SQ) {
        int r = idx >> 7, c = idx & 127;
        gwT[c * SQ + r] = gate_w[idx];
        sfT[c * SQ + r] = state_flow[idx];
    }
    float gb = gate_b[s];
    h[s] = 0.0f;
    __syncthreads();
    const float* injb = inj + (size_t)b * TQ * SQ;
    for (int t = 0; t < TQ; ++t) {
        float injv = injb[(size_t)t * SQ + s];
        float accg = gb, accf = 0.0f;
        #pragma unroll 16
        for (int k = 0; k < SQ; ++k) {
            float hk = h[k];
            accg += hk * gwT[k * SQ + s];
            accf += hk * sfT[k * SQ + s];
        }
        float hold = h[s];
        float g = 1.0f / (1.0f + expf(-(accg + injv)));
        float hn = (1.0f - g) * hold + g * accf;
        __syncthreads();
        h[s] = hn;
        size_t off = ((size_t)(b << 10) + t) * SQ + s;
        __nv_bfloat16 hh = __float2bfloat16(hn);
        hhi[off] = hh;
        hlo[off] = __float2bfloat16(hn - __bfloat162float(hh));
        __syncthreads();
    }
}

// ---- HMMA GEMM: C[M,N] = A[M,K] @ W[N,K]^T via bf16 hi/lo 3-term split ----
// EPI: 0 = fp32 store, 1 = +ext[M,N] split-store, 2 = +bias gelu split-store, 3 = +bias fp32
#define GBM 128
#define GBN 128
#define GBK 32
#define NSTG 3
#define ROWP 40                       // padded row length (bf16 elems)
#define MATB (128 * ROWP * 2)         // bytes per matrix per stage (10240)
#define STGB (4 * MATB)               // bytes per stage (40960)
#define GSMEM (NSTG * STGB)           // 122880

template <int EPI>
__global__ __launch_bounds__(256, 1)
void gemm_mma(const __nv_bfloat16* __restrict__ Ahi, const __nv_bfloat16* __restrict__ Alo,
              const __nv_bfloat16* __restrict__ Bhi, const __nv_bfloat16* __restrict__ Blo,
              const float* __restrict__ ext, float* __restrict__ outf,
              __nv_bfloat16* __restrict__ ohi, __nv_bfloat16* __restrict__ olo,
              int K, int N) {
    extern __shared__ __align__(16) unsigned char dsm[];
    const uint32_t sbase = smem_u32(dsm);
    const int tid = threadIdx.x, lane = tid & 31, wid = tid >> 5;
    const size_t mBase = (size_t)blockIdx.y * GBM, nBase = (size_t)blockIdx.x * GBN;

    // load mapping: each thread loads 2x16B per matrix per stage
    const int lrow = tid >> 1, lchunk = (tid & 1) * 2;
    const size_t aoff = (mBase + lrow) * (size_t)K + lchunk * 8;
    const size_t boff = (nBase + lrow) * (size_t)K + lchunk * 8;
    const uint32_t soff = (uint32_t)(lrow * 80 + lchunk * 16);

    const int ktiles = K / GBK;

    auto issue = [&](int st, int kt) {
        uint32_t sb = sbase + (uint32_t)st * STGB;
        size_t k0 = (size_t)kt * GBK;
        const __nv_bfloat16* pa = Ahi + aoff + k0;
        const __nv_bfloat16* pb = Alo + aoff + k0;
        const __nv_bfloat16* pc = Bhi + boff + k0;
        const __nv_bfloat16* pd = Blo + boff + k0;
        cpa16(sb + soff,                pa);     cpa16(sb + soff + 16,                pa + 8);
        cpa16(sb + MATB + soff,         pb);     cpa16(sb + MATB + soff + 16,         pb + 8);
        cpa16(sb + 2 * MATB + soff,     pc);     cpa16(sb + 2 * MATB + soff + 16,     pc + 8);
        cpa16(sb + 3 * MATB + soff,     pd);     cpa16(sb + 3 * MATB + soff + 16,     pd + 8);
        asm volatile("cp.async.commit_group;" ::: "memory");
    };

    const int npre = ktiles < 2 ? ktiles : 2;
    for (int s = 0; s < npre; ++s) issue(s, s);

    const int wy = wid >> 2, wx = wid & 3;
    const int m_w = wy * 64, n_w = wx * 32;

    float acc[4][4][4];
    #pragma unroll
    for (int i = 0; i < 4; ++i)
        #pragma unroll
        for (int j = 0; j < 4; ++j)
            #pragma unroll
            for (int e = 0; e < 4; ++e) acc[i][j][e] = 0.0f;

    for (int kt = 0; kt < ktiles; ++kt) {
        if (kt + 1 < ktiles) asm volatile("cp.async.wait_group 1;" ::: "memory");
        else                 asm volatile("cp.async.wait_group 0;" ::: "memory");
        __syncthreads();
        if (kt + 2 < ktiles) issue((kt + 2) % NSTG, kt + 2);

        const uint32_t sb = sbase + (uint32_t)(kt % NSTG) * STGB;
        const uint32_t sAh = sb, sAl = sb + MATB, sBh = sb + 2 * MATB, sBl = sb + 3 * MATB;

        #pragma unroll
        for (int kk = 0; kk < 2; ++kk) {
            const int kc = kk * 16;
            const int arow = (lane & 15);
            const int acol = kc + ((lane >> 4) << 3);
            const int brow = (lane & 7) + ((lane >> 4) << 3);
            const int bcol = kc + (lane & 8);
            uint32_t ah[4][4], al[4][4], bh[4][2], bl[4][2];
            #pragma unroll
            for (int mf = 0; mf < 4; ++mf) {
                uint32_t a = (uint32_t)((m_w + mf * 16 + arow) * ROWP + acol) * 2;
                ldsm4(ah[mf][0], ah[mf][1], ah[mf][2], ah[mf][3], sAh + a);
                ldsm4(al[mf][0], al[mf][1], al[mf][2], al[mf][3], sAl + a);
            }
            #pragma unroll
            for (int g = 0; g < 2; ++g) {
                uint32_t a = (uint32_t)((n_w + g * 16 + brow) * ROWP + bcol) * 2;
                uint32_t r0, r1, r2, r3;
                ldsm4(r0, r1, r2, r3, sBh + a);
                bh[g * 2][0] = r0; bh[g * 2][1] = r1; bh[g * 2 + 1][0] = r2; bh[g * 2 + 1][1] = r3;
                ldsm4(r0, r1, r2, r3, sBl + a);
                bl[g * 2][0] = r0; bl[g * 2][1] = r1; bl[g * 2 + 1][0] = r2; bl[g * 2 + 1][1] = r3;
            }
            #pragma unroll
            for (int mf = 0; mf < 4; ++mf)
                #pragma unroll
                for (int nf = 0; nf < 4; ++nf) {
                    mma16816(acc[mf][nf], ah[mf], bh[nf]);
                    mma16816(acc[mf][nf], ah[mf], bl[nf]);
                    mma16816(acc[mf][nf], al[mf], bh[nf]);
                }
        }
        __syncthreads();
    }

    // epilogue
    #pragma unroll
    for (int mf = 0; mf < 4; ++mf) {
        #pragma unroll
        for (int nf = 0; nf < 4; ++nf) {
            size_t r0 = mBase + m_w + mf * 16 + (lane >> 2);
            size_t cc = nBase + n_w + nf * 8 + (lane & 3) * 2;
            float v0 = acc[mf][nf][0], v1 = acc[mf][nf][1];
            float v2 = acc[mf][nf][2], v3 = acc[mf][nf][3];
            if (EPI == 1) {
                float2 e0 = *reinterpret_cast<const float2*>(ext + r0 * N + cc);
                float2 e1 = *reinterpret_cast<const float2*>(ext + (r0 + 8) * N + cc);
                v0 += e0.x; v1 += e0.y; v2 += e1.x; v3 += e1.y;
            } else if (EPI == 2 || EPI == 3) {
                float2 bb = *reinterpret_cast<const float2*>(ext + cc);
                v0 += bb.x; v1 += bb.y; v2 += bb.x; v3 += bb.y;
                if (EPI == 2) {
                    v0 = gelu_exact(v0); v1 = gelu_exact(v1);
                    v2 = gelu_exact(v2); v3 = gelu_exact(v3);
                }
            }
            if (EPI == 0 || EPI == 3) {
                float2 s0 = { v0, v1 }, s1 = { v2, v3 };
                *reinterpret_cast<float2*>(outf + r0 * N + cc) = s0;
                *reinterpret_cast<float2*>(outf + (r0 + 8) * N + cc) = s1;
            } else {
                split_store2(ohi, olo, r0 * N + cc, v0, v1);
                split_store2(ohi, olo, (r0 + 8) * N + cc, v2, v3);
            }
        }
    }
}

// ---- launch ----
extern "C" void kernel_launch(void* const* d_in, const int* in_sizes, int n_in,
                              void* d_out, int out_size) {
    const float* x          = (const float*)d_in[0];
    const float* ln1_w      = (const float*)d_in[1];
    const float* ln1_b      = (const float*)d_in[2];
    const float* state_flow = (const float*)d_in[3];
    const float* injection  = (const float*)d_in[4];
    const float* readout    = (const float*)d_in[5];
    const float* gate_w     = (const float*)d_in[6];
    const float* gate_b     = (const float*)d_in[7];
    const float* w1         = (const float*)d_in[8];
    const float* b1         = (const float*)d_in[9];
    const float* w2         = (const float*)d_in[10];
    const float* b2         = (const float*)d_in[11];
    const float* ln2_w      = (const float*)d_in[12];
    const float* ln2_b      = (const float*)d_in[13];
    float* out = (float*)d_out;

    float *lnx, *inj, *x3;
    __nv_bfloat16 *lnxh, *lnxl, *hh, *hl, *x2h, *x2l, *hbh, *hbl;
    __nv_bfloat16 *wih, *wil, *roh, *rol, *w1h, *w1l, *w2h, *w2l;
    cudaGetSymbolAddress((void**)&lnx, g_lnx);
    cudaGetSymbolAddress((void**)&lnxh, g_lnx_hi);
    cudaGetSymbolAddress((void**)&lnxl, g_lnx_lo);
    cudaGetSymbolAddress((void**)&inj, g_inj);
    cudaGetSymbolAddress((void**)&hh, g_h_hi);
    cudaGetSymbolAddress((void**)&hl, g_h_lo);
    cudaGetSymbolAddress((void**)&x2h, g_x2_hi);
    cudaGetSymbolAddress((void**)&x2l, g_x2_lo);
    cudaGetSymbolAddress((void**)&hbh, g_hb_hi);
    cudaGetSymbolAddress((void**)&hbl, g_hb_lo);
    cudaGetSymbolAddress((void**)&x3, g_x3);
    cudaGetSymbolAddress((void**)&wih, g_wi_hi);
    cudaGetSymbolAddress((void**)&wil, g_wi_lo);
    cudaGetSymbolAddress((void**)&roh, g_ro_hi);
    cudaGetSymbolAddress((void**)&rol, g_ro_lo);
    cudaGetSymbolAddress((void**)&w1h, g_w1_hi);
    cudaGetSymbolAddress((void**)&w1l, g_w1_lo);
    cudaGetSymbolAddress((void**)&w2h, g_w2_hi);
    cudaGetSymbolAddress((void**)&w2l, g_w2_lo);

    const int scan_smem = 2 * SQ * SQ * (int)sizeof(float);
    cudaFuncSetAttribute(scan_kernel, cudaFuncAttributeMaxDynamicSharedMemorySize, scan_smem);
    cudaFuncSetAttribute(gemm_mma<0>, cudaFuncAttributeMaxDynamicSharedMemorySize, GSMEM);
    cudaFuncSetAttribute(gemm_mma<1>, cudaFuncAttributeMaxDynamicSharedMemorySize, GSMEM);
    cudaFuncSetAttribute(gemm_mma<2>, cudaFuncAttributeMaxDynamicSharedMemorySize, GSMEM);
    cudaFuncSetAttribute(gemm_mma<3>, cudaFuncAttributeMaxDynamicSharedMemorySize, GSMEM);

    // weight conversions (row-major hi/lo)
    conv_split<<<(SQ * DQ / 8) / 256, 256>>>(injection, wih, wil, DQ);
    conv_split<<<(DQ * SQ / 8) / 256, 256>>>(readout, roh, rol, SQ);
    conv_split<<<(int)(((size_t)HQ * DQ / 8) / 256), 256>>>(w1, w1h, w1l, DQ);
    conv_split<<<(int)(((size_t)DQ * HQ / 8) / 256), 256>>>(w2, w2h, w2l, HQ);
    // LN1 (+split)
    ln_kernel<false, true><<<MQ, 256>>>(x, ln1_w, ln1_b, lnx, lnxh, lnxl);
    // inj = lnx @ injection^T   [M x 128], K=1024
    gemm_mma<0><<<dim3(1, MQ / GBM), 256, GSMEM>>>(lnxh, lnxl, wih, wil, nullptr, inj,
                                                   nullptr, nullptr, DQ, SQ);
    // scan -> h hi/lo
    scan_kernel<<<BQ, SQ, scan_smem>>>(gate_w, gate_b, state_flow, inj, hh, hl);
    // x2 = lnx + h @ readout^T  [M x 1024], K=128 -> split store
    gemm_mma<1><<<dim3(DQ / GBN, MQ / GBM), 256, GSMEM>>>(hh, hl, roh, rol, lnx, nullptr,
                                                          x2h, x2l, SQ, DQ);
    // hb = gelu(x2 @ w1^T + b1) [M x 4096], K=1024 -> split store
    gemm_mma<2><<<dim3(HQ / GBN, MQ / GBM), 256, GSMEM>>>(x2h, x2l, w1h, w1l, b1, nullptr,
                                                          hbh, hbl, DQ, HQ);
    // x3 = hb @ w2^T + b2       [M x 1024], K=4096 -> fp32
    gemm_mma<3><<<dim3(DQ / GBN, MQ / GBM), 256, GSMEM>>>(hbh, hbl, w2h, w2l, b2, x3,
                                                          nullptr, nullptr, HQ, DQ);
    // out = x3 + LN(x3)
    ln_kernel<true, false><<<MQ, 256>>>(x3, ln2_w, ln2_b, out, nullptr, nullptr);
}

// round 5
// speedup vs baseline: 2.3515x; 1.1811x over previous
#include <cuda_runtime.h>
#include <cuda_fp16.h>
#include <math.h>
#include <stdint.h>

#define BQ 32
#define TQ 1024
#define DQ 1024
#define SQ 128
#define HQ 4096
#define MQ (BQ * TQ)

// ---- scratch (hi/lo fp16 buffers, plain row-major) ----
__device__ __align__(16) float  g_lnx[(size_t)MQ * DQ];
__device__ __align__(16) __half g_lnx_hi[(size_t)MQ * DQ];
__device__ __align__(16) __half g_lnx_lo[(size_t)MQ * DQ];
__device__ __align__(16) float  g_inj[(size_t)MQ * SQ];
__device__ __align__(16) __half g_h_hi[(size_t)MQ * SQ];
__device__ __align__(16) __half g_h_lo[(size_t)MQ * SQ];
__device__ __align__(16) __half g_x2_hi[(size_t)MQ * DQ];
__device__ __align__(16) __half g_x2_lo[(size_t)MQ * DQ];
__device__ __align__(16) __half g_hb_hi[(size_t)MQ * HQ];
__device__ __align__(16) __half g_hb_lo[(size_t)MQ * HQ];
__device__ __align__(16) float  g_x3[(size_t)MQ * DQ];
__device__ __align__(16) __half g_wi_hi[SQ * DQ], g_wi_lo[SQ * DQ];
__device__ __align__(16) __half g_ro_hi[DQ * SQ], g_ro_lo[DQ * SQ];
__device__ __align__(16) __half g_w1_hi[(size_t)HQ * DQ], g_w1_lo[(size_t)HQ * DQ];
__device__ __align__(16) __half g_w2_hi[(size_t)DQ * HQ], g_w2_lo[(size_t)DQ * HQ];

// ---- helpers ----
__device__ __forceinline__ uint32_t smem_u32(const void* p) {
    uint32_t a;
    asm("{ .reg .u64 t; cvta.to.shared.u64 t, %1; cvt.u32.u64 %0, t; }" : "=r"(a) : "l"(p));
    return a;
}
__device__ __forceinline__ void cpa16(uint32_t s, const void* g) {
    asm volatile("cp.async.cg.shared.global [%0], [%1], 16;" :: "r"(s), "l"(g) : "memory");
}
template <int N>
__device__ __forceinline__ void wgrp() {
    asm volatile("cp.async.wait_group %0;" :: "n"(N) : "memory");
}
__device__ __forceinline__ void ldsm4(uint32_t& r0, uint32_t& r1, uint32_t& r2, uint32_t& r3, uint32_t a) {
    asm volatile("ldmatrix.sync.aligned.m8n8.x4.shared.b16 {%0,%1,%2,%3}, [%4];"
                 : "=r"(r0), "=r"(r1), "=r"(r2), "=r"(r3) : "r"(a));
}
__device__ __forceinline__ void mma16816(float* c, const uint32_t* a, const uint32_t* b) {
    asm volatile("mma.sync.aligned.m16n8k16.row.col.f32.f16.f16.f32 "
                 "{%0,%1,%2,%3}, {%4,%5,%6,%7}, {%8,%9}, {%0,%1,%2,%3};"
                 : "+f"(c[0]), "+f"(c[1]), "+f"(c[2]), "+f"(c[3])
                 : "r"(a[0]), "r"(a[1]), "r"(a[2]), "r"(a[3]), "r"(b[0]), "r"(b[1]));
}
__device__ __forceinline__ uint32_t pkh2(float a, float b) {
    __half2 t = __floats2half2_rn(a, b);
    return *reinterpret_cast<uint32_t*>(&t);
}
__device__ __forceinline__ float gelu_exact(float x) {
    return 0.5f * x * (1.0f + erff(x * 0.7071067811865476f));
}
__device__ __forceinline__ void split_store2(__half* ohi, __half* olo, size_t off, float v0, float v1) {
    __half h0 = __float2half_rn(v0), h1 = __float2half_rn(v1);
    float l0 = v0 - __half2float(h0), l1 = v1 - __half2float(h1);
    *reinterpret_cast<uint32_t*>(ohi + off) = pkh2(__half2float(h0), __half2float(h1));
    *reinterpret_cast<uint32_t*>(olo + off) = pkh2(l0, l1);
}

// ---- conversion: fp32 [R,K] -> row-major hi/lo fp16 ----
__global__ __launch_bounds__(256)
void conv_split(const float* __restrict__ in, __half* __restrict__ hi,
                __half* __restrict__ lo) {
    size_t idx = ((size_t)blockIdx.x * blockDim.x + threadIdx.x) * 8;
    const float4* p = reinterpret_cast<const float4*>(in + idx);
    float4 a = p[0], b = p[1];
    float v[8] = { a.x, a.y, a.z, a.w, b.x, b.y, b.z, b.w };
    float hf[8], lf[8];
    #pragma unroll
    for (int i = 0; i < 8; ++i) {
        __half h = __float2half_rn(v[i]);
        hf[i] = __half2float(h);
        lf[i] = v[i] - hf[i];
    }
    uint4 H = { pkh2(hf[0], hf[1]), pkh2(hf[2], hf[3]), pkh2(hf[4], hf[5]), pkh2(hf[6], hf[7]) };
    uint4 L = { pkh2(lf[0], lf[1]), pkh2(lf[2], lf[3]), pkh2(lf[4], lf[5]), pkh2(lf[6], lf[7]) };
    *reinterpret_cast<uint4*>(hi + idx) = H;
    *reinterpret_cast<uint4*>(lo + idx) = L;
}

// ---- LayerNorm ----
__device__ __forceinline__ void block_reduce2(float& a, float& b) {
    #pragma unroll
    for (int o = 16; o > 0; o >>= 1) {
        a += __shfl_xor_sync(0xFFFFFFFFu, a, o);
        b += __shfl_xor_sync(0xFFFFFFFFu, b, o);
    }
    __shared__ float sa[8], sb[8];
    int w = threadIdx.x >> 5, l = threadIdx.x & 31;
    if (l == 0) { sa[w] = a; sb[w] = b; }
    __syncthreads();
    if (w == 0) {
        a = (l < 8) ? sa[l] : 0.f;
        b = (l < 8) ? sb[l] : 0.f;
        #pragma unroll
        for (int o = 4; o > 0; o >>= 1) {
            a += __shfl_xor_sync(0xFFFFFFFFu, a, o);
            b += __shfl_xor_sync(0xFFFFFFFFu, b, o);
        }
        if (l == 0) { sa[0] = a; sb[0] = b; }
    }
    __syncthreads();
    a = sa[0]; b = sb[0];
}

template <bool RESID, bool SPLIT>
__global__ __launch_bounds__(256)
void ln_kernel(const float* __restrict__ x, const float* __restrict__ w,
               const float* __restrict__ bias, float* __restrict__ out,
               __half* __restrict__ ohi, __half* __restrict__ olo) {
    size_t row = blockIdx.x;
    float4 v = reinterpret_cast<const float4*>(x + row * DQ)[threadIdx.x];
    float s = v.x + v.y + v.z + v.w;
    float s2 = v.x * v.x + v.y * v.y + v.z * v.z + v.w * v.w;
    block_reduce2(s, s2);
    float mean = s * (1.0f / DQ);
    float rs = rsqrtf(s2 * (1.0f / DQ) - mean * mean + 1e-5f);
    float4 wv = reinterpret_cast<const float4*>(w)[threadIdx.x];
    float4 bv = reinterpret_cast<const float4*>(bias)[threadIdx.x];
    float4 o;
    o.x = (v.x - mean) * rs * wv.x + bv.x;
    o.y = (v.y - mean) * rs * wv.y + bv.y;
    o.z = (v.z - mean) * rs * wv.z + bv.z;
    o.w = (v.w - mean) * rs * wv.w + bv.w;
    if (RESID) { o.x += v.x; o.y += v.y; o.z += v.z; o.w += v.w; }
    reinterpret_cast<float4*>(out + row * DQ)[threadIdx.x] = o;
    if (SPLIT) {
        size_t off = row * DQ + 4 * threadIdx.x;
        split_store2(ohi, olo, off, o.x, o.y);
        split_store2(ohi, olo, off + 2, o.z, o.w);
    }
}

// ---- sequential scan ----
__global__ __launch_bounds__(128)
void scan_kernel(const float* __restrict__ gate_w, const float* __restrict__ gate_b,
                 const float* __restrict__ state_flow, const float* __restrict__ inj,
                 __half* __restrict__ hhi, __half* __restrict__ hlo) {
    extern __shared__ float dynsm[];
    float* gwT = dynsm;
    float* sfT = dynsm + SQ * SQ;
    __shared__ float h[SQ];
    int s = threadIdx.x, b = blockIdx.x;
    for (int idx = s; idx < SQ * SQ; idx += SQ) {
        int r = idx >> 7, c = idx & 127;
        gwT[c * SQ + r] = gate_w[idx];
        sfT[c * SQ + r] = state_flow[idx];
    }
    float gb = gate_b[s];
    h[s] = 0.0f;
    __syncthreads();
    const float* injb = inj + (size_t)b * TQ * SQ;
    for (int t = 0; t < TQ; ++t) {
        float injv = injb[(size_t)t * SQ + s];
        float accg = gb, accf = 0.0f;
        #pragma unroll 16
        for (int k = 0; k < SQ; ++k) {
            float hk = h[k];
            accg += hk * gwT[k * SQ + s];
            accf += hk * sfT[k * SQ + s];
        }
        float hold = h[s];
        float g = 1.0f / (1.0f + expf(-(accg + injv)));
        float hn = (1.0f - g) * hold + g * accf;
        __syncthreads();
        h[s] = hn;
        size_t off = ((size_t)(b << 10) + t) * SQ + s;
        __half hh = __float2half_rn(hn);
        hhi[off] = hh;
        hlo[off] = __float2half_rn(hn - __half2float(hh));
        __syncthreads();
    }
}

// ---- HMMA GEMM: C[M,N] = A[M,K] @ W[N,K]^T, fp16 split ----
// BL=true : 3-term (Ahi,Alo)x(Bhi) + Ahi x Blo   (3 smem mats + Blo, 3 stages)
// BL=false: 2-term (Ahi+Alo) x Bhi               (3 smem mats, 4 stages)
// EPI: 0=f32 store, 1=+ext[M,N] split-store, 2=+bias gelu split-store, 3=+bias f32
#define GBM 128
#define GBN 128
#define GBK 32
#define ROWP 40
#define MATB (128 * ROWP * 2)     // 10240 B
#define GSMEM 122880              // 3*4*MATB == 4*3*MATB

template <int EPI, bool BL>
__global__ __launch_bounds__(256, 1)
void gemm_mma(const __half* __restrict__ Ahi, const __half* __restrict__ Alo,
              const __half* __restrict__ Bhi, const __half* __restrict__ Blo,
              const float* __restrict__ ext, float* __restrict__ outf,
              __half* __restrict__ ohi, __half* __restrict__ olo,
              int K, int N) {
    constexpr int NSTG = BL ? 3 : 4;
    constexpr int STGB = (BL ? 4 : 3) * MATB;
    extern __shared__ __align__(16) unsigned char dsm[];
    const uint32_t sbase = smem_u32(dsm);
    const int tid = threadIdx.x, lane = tid & 31, wid = tid >> 5;
    const size_t mBase = (size_t)blockIdx.y * GBM, nBase = (size_t)blockIdx.x * GBN;

    const int lrow = tid >> 1, lchunk = (tid & 1) * 2;
    const size_t aoff = (mBase + lrow) * (size_t)K + lchunk * 8;
    const size_t boff = (nBase + lrow) * (size_t)K + lchunk * 8;
    const uint32_t soff = (uint32_t)(lrow * 80 + lchunk * 16);

    const int ktiles = K / GBK;

    auto issue = [&](int st, int kt) {
        uint32_t sb = sbase + (uint32_t)st * STGB;
        size_t k0 = (size_t)kt * GBK;
        const __half* pa = Ahi + aoff + k0;
        const __half* pb = Alo + aoff + k0;
        const __half* pc = Bhi + boff + k0;
        cpa16(sb + soff,            pa);  cpa16(sb + soff + 16,            pa + 8);
        cpa16(sb + MATB + soff,     pb);  cpa16(sb + MATB + soff + 16,     pb + 8);
        cpa16(sb + 2 * MATB + soff, pc);  cpa16(sb + 2 * MATB + soff + 16, pc + 8);
        if (BL) {
            const __half* pd = Blo + boff + k0;
            cpa16(sb + 3 * MATB + soff, pd);  cpa16(sb + 3 * MATB + soff + 16, pd + 8);
        }
        asm volatile("cp.async.commit_group;" ::: "memory");
    };

    const int npre = ktiles < NSTG - 1 ? ktiles : NSTG - 1;
    for (int s = 0; s < npre; ++s) issue(s, s);

    const int wy = wid >> 2, wx = wid & 3;
    const int m_w = wy * 64, n_w = wx * 32;

    float acc[4][4][4];
    #pragma unroll
    for (int i = 0; i < 4; ++i)
        #pragma unroll
        for (int j = 0; j < 4; ++j)
            #pragma unroll
            for (int e = 0; e < 4; ++e) acc[i][j][e] = 0.0f;

    for (int kt = 0; kt < ktiles; ++kt) {
        const int rem = ktiles - 1 - kt;
        if (NSTG == 4) {
            if (rem >= 2) wgrp<2>(); else if (rem == 1) wgrp<1>(); else wgrp<0>();
        } else {
            if (rem >= 1) wgrp<1>(); else wgrp<0>();
        }
        __syncthreads();
        if (kt + NSTG - 1 < ktiles) issue((kt + NSTG - 1) % NSTG, kt + NSTG - 1);

        const uint32_t sb = sbase + (uint32_t)(kt % NSTG) * STGB;
        const uint32_t sAh = sb, sAl = sb + MATB, sBh = sb + 2 * MATB, sBl = sb + 3 * MATB;

        #pragma unroll
        for (int kk = 0; kk < 2; ++kk) {
            const int kc = kk * 16;
            const int arow = (lane & 15);
            const int acol = kc + ((lane >> 4) << 3);
            const int brow = (lane & 7) + ((lane >> 4) << 3);
            const int bcol = kc + (lane & 8);
            uint32_t ah[4][4], al[4][4], bh[4][2], bl[4][2];
            #pragma unroll
            for (int mf = 0; mf < 4; ++mf) {
                uint32_t a = (uint32_t)((m_w + mf * 16 + arow) * ROWP + acol) * 2;
                ldsm4(ah[mf][0], ah[mf][1], ah[mf][2], ah[mf][3], sAh + a);
                ldsm4(al[mf][0], al[mf][1], al[mf][2], al[mf][3], sAl + a);
            }
            #pragma unroll
            for (int g = 0; g < 2; ++g) {
                uint32_t a = (uint32_t)((n_w + g * 16 + brow) * ROWP + bcol) * 2;
                uint32_t r0, r1, r2, r3;
                ldsm4(r0, r1, r2, r3, sBh + a);
                bh[g * 2][0] = r0; bh[g * 2][1] = r1; bh[g * 2 + 1][0] = r2; bh[g * 2 + 1][1] = r3;
                if (BL) {
                    ldsm4(r0, r1, r2, r3, sBl + a);
                    bl[g * 2][0] = r0; bl[g * 2][1] = r1; bl[g * 2 + 1][0] = r2; bl[g * 2 + 1][1] = r3;
                }
            }
            #pragma unroll
            for (int mf = 0; mf < 4; ++mf)
                #pragma unroll
                for (int nf = 0; nf < 4; ++nf) {
                    mma16816(acc[mf][nf], ah[mf], bh[nf]);
                    mma16816(acc[mf][nf], al[mf], bh[nf]);
                    if (BL) mma16816(acc[mf][nf], ah[mf], bl[nf]);
                }
        }
        __syncthreads();
    }

    // epilogue
    #pragma unroll
    for (int mf = 0; mf < 4; ++mf) {
        #pragma unroll
        for (int nf = 0; nf < 4; ++nf) {
            size_t r0 = mBase + m_w + mf * 16 + (lane >> 2);
            size_t cc = nBase + n_w + nf * 8 + (lane & 3) * 2;
            float v0 = acc[mf][nf][0], v1 = acc[mf][nf][1];
            float v2 = acc[mf][nf][2], v3 = acc[mf][nf][3];
            if (EPI == 1) {
                float2 e0 = *reinterpret_cast<const float2*>(ext + r0 * N + cc);
                float2 e1 = *reinterpret_cast<const float2*>(ext + (r0 + 8) * N + cc);
                v0 += e0.x; v1 += e0.y; v2 += e1.x; v3 += e1.y;
            } else if (EPI == 2 || EPI == 3) {
                float2 bb = *reinterpret_cast<const float2*>(ext + cc);
                v0 += bb.x; v1 += bb.y; v2 += bb.x; v3 += bb.y;
                if (EPI == 2) {
                    v0 = gelu_exact(v0); v1 = gelu_exact(v1);
                    v2 = gelu_exact(v2); v3 = gelu_exact(v3);
                }
            }
            if (EPI == 0 || EPI == 3) {
                float2 s0 = { v0, v1 }, s1 = { v2, v3 };
                *reinterpret_cast<float2*>(outf + r0 * N + cc) = s0;
                *reinterpret_cast<float2*>(outf + (r0 + 8) * N + cc) = s1;
            } else {
                split_store2(ohi, olo, r0 * N + cc, v0, v1);
                split_store2(ohi, olo, (r0 + 8) * N + cc, v2, v3);
            }
        }
    }
}

// ---- launch ----
extern "C" void kernel_launch(void* const* d_in, const int* in_sizes, int n_in,
                              void* d_out, int out_size) {
    const float* x          = (const float*)d_in[0];
    const float* ln1_w      = (const float*)d_in[1];
    const float* ln1_b      = (const float*)d_in[2];
    const float* state_flow = (const float*)d_in[3];
    const float* injection  = (const float*)d_in[4];
    const float* readout    = (const float*)d_in[5];
    const float* gate_w     = (const float*)d_in[6];
    const float* gate_b     = (const float*)d_in[7];
    const float* w1         = (const float*)d_in[8];
    const float* b1         = (const float*)d_in[9];
    const float* w2         = (const float*)d_in[10];
    const float* b2         = (const float*)d_in[11];
    const float* ln2_w      = (const float*)d_in[12];
    const float* ln2_b      = (const float*)d_in[13];
    float* out = (float*)d_out;

    float *lnx, *inj, *x3;
    __half *lnxh, *lnxl, *hh, *hl, *x2h, *x2l, *hbh, *hbl;
    __half *wih, *wil, *roh, *rol, *w1h, *w1l, *w2h, *w2l;
    cudaGetSymbolAddress((void**)&lnx, g_lnx);
    cudaGetSymbolAddress((void**)&lnxh, g_lnx_hi);
    cudaGetSymbolAddress((void**)&lnxl, g_lnx_lo);
    cudaGetSymbolAddress((void**)&inj, g_inj);
    cudaGetSymbolAddress((void**)&hh, g_h_hi);
    cudaGetSymbolAddress((void**)&hl, g_h_lo);
    cudaGetSymbolAddress((void**)&x2h, g_x2_hi);
    cudaGetSymbolAddress((void**)&x2l, g_x2_lo);
    cudaGetSymbolAddress((void**)&hbh, g_hb_hi);
    cudaGetSymbolAddress((void**)&hbl, g_hb_lo);
    cudaGetSymbolAddress((void**)&x3, g_x3);
    cudaGetSymbolAddress((void**)&wih, g_wi_hi);
    cudaGetSymbolAddress((void**)&wil, g_wi_lo);
    cudaGetSymbolAddress((void**)&roh, g_ro_hi);
    cudaGetSymbolAddress((void**)&rol, g_ro_lo);
    cudaGetSymbolAddress((void**)&w1h, g_w1_hi);
    cudaGetSymbolAddress((void**)&w1l, g_w1_lo);
    cudaGetSymbolAddress((void**)&w2h, g_w2_hi);
    cudaGetSymbolAddress((void**)&w2l, g_w2_lo);

    const int scan_smem = 2 * SQ * SQ * (int)sizeof(float);
    cudaFuncSetAttribute(scan_kernel, cudaFuncAttributeMaxDynamicSharedMemorySize, scan_smem);
    cudaFuncSetAttribute(gemm_mma<0, true>,  cudaFuncAttributeMaxDynamicSharedMemorySize, GSMEM);
    cudaFuncSetAttribute(gemm_mma<1, false>, cudaFuncAttributeMaxDynamicSharedMemorySize, GSMEM);
    cudaFuncSetAttribute(gemm_mma<2, false>, cudaFuncAttributeMaxDynamicSharedMemorySize, GSMEM);
    cudaFuncSetAttribute(gemm_mma<3, false>, cudaFuncAttributeMaxDynamicSharedMemorySize, GSMEM);

    // weight conversions (row-major hi/lo fp16)
    conv_split<<<(SQ * DQ / 8) / 256, 256>>>(injection, wih, wil);
    conv_split<<<(DQ * SQ / 8) / 256, 256>>>(readout, roh, rol);
    conv_split<<<(int)(((size_t)HQ * DQ / 8) / 256), 256>>>(w1, w1h, w1l);
    conv_split<<<(int)(((size_t)DQ * HQ / 8) / 256), 256>>>(w2, w2h, w2l);
    // LN1 (+split)
    ln_kernel<false, true><<<MQ, 256>>>(x, ln1_w, ln1_b, lnx, lnxh, lnxl);
    // inj = lnx @ injection^T   [M x 128], K=1024   (3-term: protects the scan)
    gemm_mma<0, true><<<dim3(1, MQ / GBM), 256, GSMEM>>>(lnxh, lnxl, wih, wil, nullptr, inj,
                                                         nullptr, nullptr, DQ, SQ);
    // scan -> h hi/lo
    scan_kernel<<<BQ, SQ, scan_smem>>>(gate_w, gate_b, state_flow, inj, hh, hl);
    // x2 = lnx + h @ readout^T  [M x 1024], K=128   (2-term)
    gemm_mma<1, false><<<dim3(DQ / GBN, MQ / GBM), 256, GSMEM>>>(hh, hl, roh, nullptr, lnx,
                                                                 nullptr, x2h, x2l, SQ, DQ);
    // hb = gelu(x2 @ w1^T + b1) [M x 4096], K=1024  (2-term)
    gemm_mma<2, false><<<dim3(HQ / GBN, MQ / GBM), 256, GSMEM>>>(x2h, x2l, w1h, nullptr, b1,
                                                                 nullptr, hbh, hbl, DQ, HQ);
    // x3 = hb @ w2^T + b2       [M x 1024], K=4096  (2-term)
    gemm_mma<3, false><<<dim3(DQ / GBN, MQ / GBM), 256, GSMEM>>>(hbh, hbl, w2h, nullptr, b2,
                                                                 x3, nullptr, nullptr, HQ, DQ);
    // out = x3 + LN(x3)
    ln_kernel<true, false><<<MQ, 256>>>(x3, ln2_w, ln2_b, out, nullptr, nullptr);
}

// round 6
// speedup vs baseline: 3.1265x; 1.3296x over previous
#include <cuda_runtime.h>
#include <cuda_fp16.h>
#include <math.h>
#include <stdint.h>

#define BQ 32
#define TQ 1024
#define DQ 1024
#define SQ 128
#define HQ 4096
#define MQ (BQ * TQ)

// ---- scratch (hi/lo fp16 buffers, plain row-major) ----
__device__ __align__(16) float  g_lnx[(size_t)MQ * DQ];
__device__ __align__(16) __half g_lnx_hi[(size_t)MQ * DQ];
__device__ __align__(16) __half g_lnx_lo[(size_t)MQ * DQ];
__device__ __align__(16) float  g_inj[(size_t)MQ * SQ];
__device__ __align__(16) __half g_h_hi[(size_t)MQ * SQ];
__device__ __align__(16) __half g_h_lo[(size_t)MQ * SQ];
__device__ __align__(16) __half g_x2_hi[(size_t)MQ * DQ];
__device__ __align__(16) __half g_x2_lo[(size_t)MQ * DQ];
__device__ __align__(16) __half g_hb_hi[(size_t)MQ * HQ];
__device__ __align__(16) __half g_hb_lo[(size_t)MQ * HQ];
__device__ __align__(16) float  g_x3[(size_t)MQ * DQ];
__device__ __align__(16) __half g_wi_hi[SQ * DQ], g_wi_lo[SQ * DQ];
__device__ __align__(16) __half g_ro_hi[DQ * SQ], g_ro_lo[DQ * SQ];
__device__ __align__(16) __half g_w1_hi[(size_t)HQ * DQ], g_w1_lo[(size_t)HQ * DQ];
__device__ __align__(16) __half g_w2_hi[(size_t)DQ * HQ], g_w2_lo[(size_t)DQ * HQ];

// ---- helpers ----
__device__ __forceinline__ uint32_t smem_u32(const void* p) {
    uint32_t a;
    asm("{ .reg .u64 t; cvta.to.shared.u64 t, %1; cvt.u32.u64 %0, t; }" : "=r"(a) : "l"(p));
    return a;
}
__device__ __forceinline__ void cpa16(uint32_t s, const void* g) {
    asm volatile("cp.async.cg.shared.global [%0], [%1], 16;" :: "r"(s), "l"(g) : "memory");
}
template <int N>
__device__ __forceinline__ void wgrp() {
    asm volatile("cp.async.wait_group %0;" :: "n"(N) : "memory");
}
__device__ __forceinline__ void ldsm4(uint32_t& r0, uint32_t& r1, uint32_t& r2, uint32_t& r3, uint32_t a) {
    asm volatile("ldmatrix.sync.aligned.m8n8.x4.shared.b16 {%0,%1,%2,%3}, [%4];"
                 : "=r"(r0), "=r"(r1), "=r"(r2), "=r"(r3) : "r"(a));
}
__device__ __forceinline__ void mma16816(float* c, const uint32_t* a, const uint32_t* b) {
    asm volatile("mma.sync.aligned.m16n8k16.row.col.f32.f16.f16.f32 "
                 "{%0,%1,%2,%3}, {%4,%5,%6,%7}, {%8,%9}, {%0,%1,%2,%3};"
                 : "+f"(c[0]), "+f"(c[1]), "+f"(c[2]), "+f"(c[3])
                 : "r"(a[0]), "r"(a[1]), "r"(a[2]), "r"(a[3]), "r"(b[0]), "r"(b[1]));
}
__device__ __forceinline__ uint32_t pkh2(float a, float b) {
    __half2 t = __floats2half2_rn(a, b);
    return *reinterpret_cast<uint32_t*>(&t);
}
__device__ __forceinline__ unsigned long long pk2(float lo, float hi) {
    unsigned long long r;
    asm("mov.b64 %0, {%1, %2};" : "=l"(r) : "r"(__float_as_uint(lo)), "r"(__float_as_uint(hi)));
    return r;
}
__device__ __forceinline__ void fma2(unsigned long long& d, unsigned long long a, unsigned long long b) {
    asm("fma.rn.f32x2 %0, %1, %2, %3;" : "=l"(d) : "l"(a), "l"(b), "l"(d));
}
__device__ __forceinline__ float gelu_exact(float x) {
    return 0.5f * x * (1.0f + erff(x * 0.7071067811865476f));
}
__device__ __forceinline__ void split_store2(__half* ohi, __half* olo, size_t off, float v0, float v1) {
    __half h0 = __float2half_rn(v0), h1 = __float2half_rn(v1);
    float l0 = v0 - __half2float(h0), l1 = v1 - __half2float(h1);
    *reinterpret_cast<uint32_t*>(ohi + off) = pkh2(__half2float(h0), __half2float(h1));
    *reinterpret_cast<uint32_t*>(olo + off) = pkh2(l0, l1);
}

// ---- conversion: fp32 -> row-major hi/lo fp16 ----
__global__ __launch_bounds__(256)
void conv_split(const float* __restrict__ in, __half* __restrict__ hi,
                __half* __restrict__ lo) {
    size_t idx = ((size_t)blockIdx.x * blockDim.x + threadIdx.x) * 8;
    const float4* p = reinterpret_cast<const float4*>(in + idx);
    float4 a = p[0], b = p[1];
    float v[8] = { a.x, a.y, a.z, a.w, b.x, b.y, b.z, b.w };
    float hf[8], lf[8];
    #pragma unroll
    for (int i = 0; i < 8; ++i) {
        __half h = __float2half_rn(v[i]);
        hf[i] = __half2float(h);
        lf[i] = v[i] - hf[i];
    }
    uint4 H = { pkh2(hf[0], hf[1]), pkh2(hf[2], hf[3]), pkh2(hf[4], hf[5]), pkh2(hf[6], hf[7]) };
    uint4 L = { pkh2(lf[0], lf[1]), pkh2(lf[2], lf[3]), pkh2(lf[4], lf[5]), pkh2(lf[6], lf[7]) };
    *reinterpret_cast<uint4*>(hi + idx) = H;
    *reinterpret_cast<uint4*>(lo + idx) = L;
}

// ---- LayerNorm ----
__device__ __forceinline__ void block_reduce2(float& a, float& b) {
    #pragma unroll
    for (int o = 16; o > 0; o >>= 1) {
        a += __shfl_xor_sync(0xFFFFFFFFu, a, o);
        b += __shfl_xor_sync(0xFFFFFFFFu, b, o);
    }
    __shared__ float sa[8], sb[8];
    int w = threadIdx.x >> 5, l = threadIdx.x & 31;
    if (l == 0) { sa[w] = a; sb[w] = b; }
    __syncthreads();
    if (w == 0) {
        a = (l < 8) ? sa[l] : 0.f;
        b = (l < 8) ? sb[l] : 0.f;
        #pragma unroll
        for (int o = 4; o > 0; o >>= 1) {
            a += __shfl_xor_sync(0xFFFFFFFFu, a, o);
            b += __shfl_xor_sync(0xFFFFFFFFu, b, o);
        }
        if (l == 0) { sa[0] = a; sb[0] = b; }
    }
    __syncthreads();
    a = sa[0]; b = sb[0];
}

template <bool RESID, bool SPLIT>
__global__ __launch_bounds__(256)
void ln_kernel(const float* __restrict__ x, const float* __restrict__ w,
               const float* __restrict__ bias, float* __restrict__ out,
               __half* __restrict__ ohi, __half* __restrict__ olo) {
    size_t row = blockIdx.x;
    float4 v = reinterpret_cast<const float4*>(x + row * DQ)[threadIdx.x];
    float s = v.x + v.y + v.z + v.w;
    float s2 = v.x * v.x + v.y * v.y + v.z * v.z + v.w * v.w;
    block_reduce2(s, s2);
    float mean = s * (1.0f / DQ);
    float rs = rsqrtf(s2 * (1.0f / DQ) - mean * mean + 1e-5f);
    float4 wv = reinterpret_cast<const float4*>(w)[threadIdx.x];
    float4 bv = reinterpret_cast<const float4*>(bias)[threadIdx.x];
    float4 o;
    o.x = (v.x - mean) * rs * wv.x + bv.x;
    o.y = (v.y - mean) * rs * wv.y + bv.y;
    o.z = (v.z - mean) * rs * wv.z + bv.z;
    o.w = (v.w - mean) * rs * wv.w + bv.w;
    if (RESID) { o.x += v.x; o.y += v.y; o.z += v.z; o.w += v.w; }
    reinterpret_cast<float4*>(out + row * DQ)[threadIdx.x] = o;
    if (SPLIT) {
        size_t off = row * DQ + 4 * threadIdx.x;
        split_store2(ohi, olo, off, o.x, o.y);
        split_store2(ohi, olo, off + 2, o.z, o.w);
    }
}

// ---- scan v2: 256 threads, register weights, packed f32x2 FMA ----
__global__ __launch_bounds__(256)
void scan_kernel(const float* __restrict__ gate_w, const float* __restrict__ gate_b,
                 const float* __restrict__ state_flow, const float* __restrict__ inj,
                 __half* __restrict__ hhi, __half* __restrict__ hlo) {
    __shared__ float h[SQ];
    __shared__ __align__(8) unsigned long long part[256];
    const int tid = threadIdx.x;
    const int s = tid & 127;
    const int half = tid >> 7;
    const int b = blockIdx.x;

    // each thread caches 64 (gate, flow) weight pairs, packed f32x2
    unsigned long long wv[64];
    #pragma unroll
    for (int j = 0; j < 64; ++j) {
        int k = half * 64 + j;
        wv[j] = pk2(gate_w[s * SQ + k], state_flow[s * SQ + k]);
    }
    float gb = (half == 0) ? gate_b[s] : 0.0f;
    if (half == 0) h[s] = 0.0f;
    __syncthreads();

    const float* injb = inj + (size_t)b * TQ * SQ;
    for (int t = 0; t < TQ; ++t) {
        float injv = (half == 0) ? injb[(size_t)t * SQ + s] : 0.0f;
        unsigned long long acc2 = 0ull;
        #pragma unroll
        for (int j = 0; j < 64; ++j) {
            float hk = h[half * 64 + j];
            fma2(acc2, pk2(hk, hk), wv[j]);
        }
        part[tid] = acc2;
        __syncthreads();
        if (half == 0) {
            float2 p0 = *reinterpret_cast<float2*>(&part[s]);
            float2 p1 = *reinterpret_cast<float2*>(&part[s + 128]);
            float accg = p0.x + p1.x + gb + injv;
            float accf = p0.y + p1.y;
            float hold = h[s];
            float g = 1.0f / (1.0f + expf(-accg));
            float hn = (1.0f - g) * hold + g * accf;
            h[s] = hn;
            size_t off = ((size_t)(b << 10) + t) * SQ + s;
            __half hh = __float2half_rn(hn);
            hhi[off] = hh;
            hlo[off] = __float2half_rn(hn - __half2float(hh));
        }
        __syncthreads();
    }
}

// ---- narrow HMMA GEMM (128x128, 3-term, for inj) ----
#define ROWP 40
#define MATB (128 * ROWP * 2)
#define NGSM 122880

__global__ __launch_bounds__(256, 1)
void gemm_inj(const __half* __restrict__ Ahi, const __half* __restrict__ Alo,
              const __half* __restrict__ Bhi, const __half* __restrict__ Blo,
              float* __restrict__ outf, int K, int N) {
    constexpr int NSTG = 3;
    constexpr int STGB = 4 * MATB;
    extern __shared__ __align__(16) unsigned char dsm[];
    const uint32_t sbase = smem_u32(dsm);
    const int tid = threadIdx.x, lane = tid & 31, wid = tid >> 5;
    const size_t mBase = (size_t)blockIdx.y * 128, nBase = (size_t)blockIdx.x * 128;

    const int lrow = tid >> 1, lchunk = (tid & 1) * 2;
    const size_t aoff = (mBase + lrow) * (size_t)K + lchunk * 8;
    const size_t boff = (nBase + lrow) * (size_t)K + lchunk * 8;
    const uint32_t soff = (uint32_t)(lrow * 80 + lchunk * 16);
    const int ktiles = K / 32;

    auto issue = [&](int st, int kt) {
        uint32_t sb = sbase + (uint32_t)st * STGB;
        size_t k0 = (size_t)kt * 32;
        const __half* pa = Ahi + aoff + k0;
        const __half* pb = Alo + aoff + k0;
        const __half* pc = Bhi + boff + k0;
        const __half* pd = Blo + boff + k0;
        cpa16(sb + soff,            pa);  cpa16(sb + soff + 16,            pa + 8);
        cpa16(sb + MATB + soff,     pb);  cpa16(sb + MATB + soff + 16,     pb + 8);
        cpa16(sb + 2 * MATB + soff, pc);  cpa16(sb + 2 * MATB + soff + 16, pc + 8);
        cpa16(sb + 3 * MATB + soff, pd);  cpa16(sb + 3 * MATB + soff + 16, pd + 8);
        asm volatile("cp.async.commit_group;" ::: "memory");
    };
    for (int s = 0; s < 2; ++s) issue(s, s);

    const int wy = wid >> 2, wx = wid & 3;
    const int m_w = wy * 64, n_w = wx * 32;
    float acc[4][4][4];
    #pragma unroll
    for (int i = 0; i < 4; ++i)
        #pragma unroll
        for (int j = 0; j < 4; ++j)
            #pragma unroll
            for (int e = 0; e < 4; ++e) acc[i][j][e] = 0.0f;

    for (int kt = 0; kt < ktiles; ++kt) {
        if (ktiles - 1 - kt >= 1) wgrp<1>(); else wgrp<0>();
        __syncthreads();
        if (kt + 2 < ktiles) issue((kt + 2) % NSTG, kt + 2);
        const uint32_t sb = sbase + (uint32_t)(kt % NSTG) * STGB;
        const uint32_t sAh = sb, sAl = sb + MATB, sBh = sb + 2 * MATB, sBl = sb + 3 * MATB;
        #pragma unroll
        for (int kk = 0; kk < 2; ++kk) {
            const int kc = kk * 16;
            const int arow = (lane & 15);
            const int acol = kc + ((lane >> 4) << 3);
            const int brow = (lane & 7) + ((lane >> 4) << 3);
            const int bcol = kc + (lane & 8);
            uint32_t ah[4][4], al[4][4], bh[4][2], bl[4][2];
            #pragma unroll
            for (int mf = 0; mf < 4; ++mf) {
                uint32_t a = (uint32_t)((m_w + mf * 16 + arow) * ROWP + acol) * 2;
                ldsm4(ah[mf][0], ah[mf][1], ah[mf][2], ah[mf][3], sAh + a);
                ldsm4(al[mf][0], al[mf][1], al[mf][2], al[mf][3], sAl + a);
            }
            #pragma unroll
            for (int g = 0; g < 2; ++g) {
                uint32_t a = (uint32_t)((n_w + g * 16 + brow) * ROWP + bcol) * 2;
                uint32_t r0, r1, r2, r3;
                ldsm4(r0, r1, r2, r3, sBh + a);
                bh[g * 2][0] = r0; bh[g * 2][1] = r1; bh[g * 2 + 1][0] = r2; bh[g * 2 + 1][1] = r3;
                ldsm4(r0, r1, r2, r3, sBl + a);
                bl[g * 2][0] = r0; bl[g * 2][1] = r1; bl[g * 2 + 1][0] = r2; bl[g * 2 + 1][1] = r3;
            }
            #pragma unroll
            for (int mf = 0; mf < 4; ++mf)
                #pragma unroll
                for (int nf = 0; nf < 4; ++nf) {
                    mma16816(acc[mf][nf], ah[mf], bh[nf]);
                    mma16816(acc[mf][nf], al[mf], bh[nf]);
                    mma16816(acc[mf][nf], ah[mf], bl[nf]);
                }
        }
        __syncthreads();
    }
    #pragma unroll
    for (int mf = 0; mf < 4; ++mf)
        #pragma unroll
        for (int nf = 0; nf < 4; ++nf) {
            size_t r0 = mBase + m_w + mf * 16 + (lane >> 2);
            size_t cc = nBase + n_w + nf * 8 + (lane & 3) * 2;
            float2 s0 = { acc[mf][nf][0], acc[mf][nf][1] };
            float2 s1 = { acc[mf][nf][2], acc[mf][nf][3] };
            *reinterpret_cast<float2*>(outf + r0 * N + cc) = s0;
            *reinterpret_cast<float2*>(outf + (r0 + 8) * N + cc) = s1;
        }
}

// ---- wide HMMA GEMM (128x256, 2-term) ----
// EPI: 1=+ext[M,N] split-store, 2=+bias gelu split-store, 3=+bias f32 store
#define W_AB 10240
#define W_BB 20480
#define W_STG 40960
#define W_NSTG 4
#define W_SMEM (W_NSTG * W_STG)   // 163840

template <int EPI>
__global__ __launch_bounds__(256, 1)
void gemm_w(const __half* __restrict__ Ahi, const __half* __restrict__ Alo,
            const __half* __restrict__ Bhi,
            const float* __restrict__ ext, float* __restrict__ outf,
            __half* __restrict__ ohi, __half* __restrict__ olo,
            int K, int N) {
    extern __shared__ __align__(16) unsigned char dsm[];
    const uint32_t sbase = smem_u32(dsm);
    const int tid = threadIdx.x, lane = tid & 31, wid = tid >> 5;
    const size_t mBase = (size_t)blockIdx.y * 128, nBase = (size_t)blockIdx.x * 256;

    const int lrow = tid >> 1, lchunk = (tid & 1) * 2;
    const size_t aoff  = (mBase + lrow) * (size_t)K + lchunk * 8;
    const size_t boff0 = (nBase + lrow) * (size_t)K + lchunk * 8;
    const size_t boff1 = (nBase + lrow + 128) * (size_t)K + lchunk * 8;
    const uint32_t soff  = (uint32_t)(lrow * 80 + lchunk * 16);
    const uint32_t soff1 = (uint32_t)((lrow + 128) * 80 + lchunk * 16);
    const int ktiles = K / 32;

    auto issue = [&](int st, int kt) {
        uint32_t sb = sbase + (uint32_t)st * W_STG;
        size_t k0 = (size_t)kt * 32;
        const __half* pa = Ahi + aoff + k0;
        const __half* pb = Alo + aoff + k0;
        const __half* pc = Bhi + boff0 + k0;
        const __half* pd = Bhi + boff1 + k0;
        cpa16(sb + soff,             pa);  cpa16(sb + soff + 16,             pa + 8);
        cpa16(sb + W_AB + soff,      pb);  cpa16(sb + W_AB + soff + 16,      pb + 8);
        cpa16(sb + 2 * W_AB + soff,  pc);  cpa16(sb + 2 * W_AB + soff + 16,  pc + 8);
        cpa16(sb + 2 * W_AB + soff1, pd);  cpa16(sb + 2 * W_AB + soff1 + 16, pd + 8);
        asm volatile("cp.async.commit_group;" ::: "memory");
    };
    const int npre = ktiles < 3 ? ktiles : 3;
    for (int s = 0; s < npre; ++s) issue(s, s);

    const int wy = wid >> 2, wx = wid & 3;
    const int m_w = wy * 64, n_w = wx * 64;

    float acc[4][8][4];
    #pragma unroll
    for (int i = 0; i < 4; ++i)
        #pragma unroll
        for (int j = 0; j < 8; ++j)
            #pragma unroll
            for (int e = 0; e < 4; ++e) acc[i][j][e] = 0.0f;

    for (int kt = 0; kt < ktiles; ++kt) {
        const int rem = ktiles - 1 - kt;
        if (rem >= 2) wgrp<2>(); else if (rem == 1) wgrp<1>(); else wgrp<0>();
        __syncthreads();
        if (kt + 3 < ktiles) issue((kt + 3) % W_NSTG, kt + 3);

        const uint32_t sb = sbase + (uint32_t)(kt % W_NSTG) * W_STG;
        const uint32_t sAh = sb, sAl = sb + W_AB, sBh = sb + 2 * W_AB;

        #pragma unroll
        for (int kk = 0; kk < 2; ++kk) {
            const int kc = kk * 16;
            const int arow = (lane & 15);
            const int acol = kc + ((lane >> 4) << 3);
            const int brow = (lane & 7) + ((lane >> 4) << 3);
            const int bcol = kc + (lane & 8);
            uint32_t ah[4][4], al[4][4], bh[8][2];
            #pragma unroll
            for (int mf = 0; mf < 4; ++mf) {
                uint32_t a = (uint32_t)((m_w + mf * 16 + arow) * ROWP + acol) * 2;
                ldsm4(ah[mf][0], ah[mf][1], ah[mf][2], ah[mf][3], sAh + a);
                ldsm4(al[mf][0], al[mf][1], al[mf][2], al[mf][3], sAl + a);
            }
            #pragma unroll
            for (int g = 0; g < 4; ++g) {
                uint32_t a = (uint32_t)((n_w + g * 16 + brow) * ROWP + bcol) * 2;
                uint32_t r0, r1, r2, r3;
                ldsm4(r0, r1, r2, r3, sBh + a);
                bh[g * 2][0] = r0; bh[g * 2][1] = r1; bh[g * 2 + 1][0] = r2; bh[g * 2 + 1][1] = r3;
            }
            #pragma unroll
            for (int mf = 0; mf < 4; ++mf)
                #pragma unroll
                for (int nf = 0; nf < 8; ++nf) {
                    mma16816(acc[mf][nf], ah[mf], bh[nf]);
                    mma16816(acc[mf][nf], al[mf], bh[nf]);
                }
        }
        __syncthreads();
    }

    #pragma unroll
    for (int mf = 0; mf < 4; ++mf) {
        #pragma unroll
        for (int nf = 0; nf < 8; ++nf) {
            size_t r0 = mBase + m_w + mf * 16 + (lane >> 2);
            size_t cc = nBase + n_w + nf * 8 + (lane & 3) * 2;
            float v0 = acc[mf][nf][0], v1 = acc[mf][nf][1];
            float v2 = acc[mf][nf][2], v3 = acc[mf][nf][3];
            if (EPI == 1) {
                float2 e0 = *reinterpret_cast<const float2*>(ext + r0 * N + cc);
                float2 e1 = *reinterpret_cast<const float2*>(ext + (r0 + 8) * N + cc);
                v0 += e0.x; v1 += e0.y; v2 += e1.x; v3 += e1.y;
            } else {
                float2 bb = *reinterpret_cast<const float2*>(ext + cc);
                v0 += bb.x; v1 += bb.y; v2 += bb.x; v3 += bb.y;
                if (EPI == 2) {
                    v0 = gelu_exact(v0); v1 = gelu_exact(v1);
                    v2 = gelu_exact(v2); v3 = gelu_exact(v3);
                }
            }
            if (EPI == 3) {
                float2 s0 = { v0, v1 }, s1 = { v2, v3 };
                *reinterpret_cast<float2*>(outf + r0 * N + cc) = s0;
                *reinterpret_cast<float2*>(outf + (r0 + 8) * N + cc) = s1;
            } else {
                split_store2(ohi, olo, r0 * N + cc, v0, v1);
                split_store2(ohi, olo, (r0 + 8) * N + cc, v2, v3);
            }
        }
    }
}

// ---- launch ----
extern "C" void kernel_launch(void* const* d_in, const int* in_sizes, int n_in,
                              void* d_out, int out_size) {
    const float* x          = (const float*)d_in[0];
    const float* ln1_w      = (const float*)d_in[1];
    const float* ln1_b      = (const float*)d_in[2];
    const float* state_flow = (const float*)d_in[3];
    const float* injection  = (const float*)d_in[4];
    const float* readout    = (const float*)d_in[5];
    const float* gate_w     = (const float*)d_in[6];
    const float* gate_b     = (const float*)d_in[7];
    const float* w1         = (const float*)d_in[8];
    const float* b1         = (const float*)d_in[9];
    const float* w2         = (const float*)d_in[10];
    const float* b2         = (const float*)d_in[11];
    const float* ln2_w      = (const float*)d_in[12];
    const float* ln2_b      = (const float*)d_in[13];
    float* out = (float*)d_out;

    float *lnx, *inj, *x3;
    __half *lnxh, *lnxl, *hh, *hl, *x2h, *x2l, *hbh, *hbl;
    __half *wih, *wil, *roh, *rol, *w1h, *w1l, *w2h, *w2l;
    cudaGetSymbolAddress((void**)&lnx, g_lnx);
    cudaGetSymbolAddress((void**)&lnxh, g_lnx_hi);
    cudaGetSymbolAddress((void**)&lnxl, g_lnx_lo);
    cudaGetSymbolAddress((void**)&inj, g_inj);
    cudaGetSymbolAddress((void**)&hh, g_h_hi);
    cudaGetSymbolAddress((void**)&hl, g_h_lo);
    cudaGetSymbolAddress((void**)&x2h, g_x2_hi);
    cudaGetSymbolAddress((void**)&x2l, g_x2_lo);
    cudaGetSymbolAddress((void**)&hbh, g_hb_hi);
    cudaGetSymbolAddress((void**)&hbl, g_hb_lo);
    cudaGetSymbolAddress((void**)&x3, g_x3);
    cudaGetSymbolAddress((void**)&wih, g_wi_hi);
    cudaGetSymbolAddress((void**)&wil, g_wi_lo);
    cudaGetSymbolAddress((void**)&roh, g_ro_hi);
    cudaGetSymbolAddress((void**)&rol, g_ro_lo);
    cudaGetSymbolAddress((void**)&w1h, g_w1_hi);
    cudaGetSymbolAddress((void**)&w1l, g_w1_lo);
    cudaGetSymbolAddress((void**)&w2h, g_w2_hi);
    cudaGetSymbolAddress((void**)&w2l, g_w2_lo);

    cudaFuncSetAttribute(gemm_inj,  cudaFuncAttributeMaxDynamicSharedMemorySize, NGSM);
    cudaFuncSetAttribute(gemm_w<1>, cudaFuncAttributeMaxDynamicSharedMemorySize, W_SMEM);
    cudaFuncSetAttribute(gemm_w<2>, cudaFuncAttributeMaxDynamicSharedMemorySize, W_SMEM);
    cudaFuncSetAttribute(gemm_w<3>, cudaFuncAttributeMaxDynamicSharedMemorySize, W_SMEM);

    // weight conversions (row-major hi/lo fp16)
    conv_split<<<(SQ * DQ / 8) / 256, 256>>>(injection, wih, wil);
    conv_split<<<(DQ * SQ / 8) / 256, 256>>>(readout, roh, rol);
    conv_split<<<(int)(((size_t)HQ * DQ / 8) / 256), 256>>>(w1, w1h, w1l);
    conv_split<<<(int)(((size_t)DQ * HQ / 8) / 256), 256>>>(w2, w2h, w2l);
    // LN1 (+split)
    ln_kernel<false, true><<<MQ, 256>>>(x, ln1_w, ln1_b, lnx, lnxh, lnxl);
    // inj = lnx @ injection^T   [M x 128], K=1024  (3-term narrow)
    gemm_inj<<<dim3(1, MQ / 128), 256, NGSM>>>(lnxh, lnxl, wih, wil, inj, DQ, SQ);
    // scan -> h hi/lo
    scan_kernel<<<BQ, 256>>>(gate_w, gate_b, state_flow, inj, hh, hl);
    // x2 = lnx + h @ readout^T  [M x 1024], K=128  (2-term wide)
    gemm_w<1><<<dim3(DQ / 256, MQ / 128), 256, W_SMEM>>>(hh, hl, roh, lnx, nullptr,
                                                         x2h, x2l, SQ, DQ);
    // hb = gelu(x2 @ w1^T + b1) [M x 4096], K=1024 (2-term wide)
    gemm_w<2><<<dim3(HQ / 256, MQ / 128), 256, W_SMEM>>>(x2h, x2l, w1h, b1, nullptr,
                                                         hbh, hbl, DQ, HQ);
    // x3 = hb @ w2^T + b2       [M x 1024], K=4096 (2-term wide)
    gemm_w<3><<<dim3(DQ / 256, MQ / 128), 256, W_SMEM>>>(hbh, hbl, w2h, b2, x3,
                                                         nullptr, nullptr, HQ, DQ);
    // out = x3 + LN(x3)
    ln_kernel<true, false><<<MQ, 256>>>(x3, ln2_w, ln2_b, out, nullptr, nullptr);
}

// round 7
// speedup vs baseline: 3.6857x; 1.1789x over previous
#include <cuda_runtime.h>
#include <cuda_fp16.h>
#include <math.h>
#include <stdint.h>

#define BQ 32
#define TQ 1024
#define DQ 1024
#define SQ 128
#define HQ 4096
#define MQ (BQ * TQ)

// ---- scratch (hi/lo fp16 buffers, plain row-major) ----
__device__ __align__(16) float  g_lnx[(size_t)MQ * DQ];
__device__ __align__(16) __half g_lnx_hi[(size_t)MQ * DQ];
__device__ __align__(16) __half g_lnx_lo[(size_t)MQ * DQ];
__device__ __align__(16) float  g_inj[(size_t)MQ * SQ];
__device__ __align__(16) __half g_h_hi[(size_t)MQ * SQ];
__device__ __align__(16) __half g_h_lo[(size_t)MQ * SQ];
__device__ __align__(16) __half g_x2_hi[(size_t)MQ * DQ];
__device__ __align__(16) __half g_x2_lo[(size_t)MQ * DQ];
__device__ __align__(16) __half g_hb_hi[(size_t)MQ * HQ];
__device__ __align__(16) float  g_x3[(size_t)MQ * DQ];
__device__ __align__(16) __half g_wi_hi[SQ * DQ], g_wi_lo[SQ * DQ];
__device__ __align__(16) __half g_ro_hi[DQ * SQ];
__device__ __align__(16) __half g_w1_hi[(size_t)HQ * DQ];
__device__ __align__(16) __half g_w2_hi[(size_t)DQ * HQ];

// ---- helpers ----
__device__ __forceinline__ uint32_t smem_u32(const void* p) {
    uint32_t a;
    asm("{ .reg .u64 t; cvta.to.shared.u64 t, %1; cvt.u32.u64 %0, t; }" : "=r"(a) : "l"(p));
    return a;
}
__device__ __forceinline__ void cpa16(uint32_t s, const void* g) {
    asm volatile("cp.async.cg.shared.global [%0], [%1], 16;" :: "r"(s), "l"(g) : "memory");
}
template <int N>
__device__ __forceinline__ void wgrp() {
    asm volatile("cp.async.wait_group %0;" :: "n"(N) : "memory");
}
__device__ __forceinline__ void ldsm4(uint32_t& r0, uint32_t& r1, uint32_t& r2, uint32_t& r3, uint32_t a) {
    asm volatile("ldmatrix.sync.aligned.m8n8.x4.shared.b16 {%0,%1,%2,%3}, [%4];"
                 : "=r"(r0), "=r"(r1), "=r"(r2), "=r"(r3) : "r"(a));
}
__device__ __forceinline__ void mma16816(float* c, const uint32_t* a, const uint32_t* b) {
    asm volatile("mma.sync.aligned.m16n8k16.row.col.f32.f16.f16.f32 "
                 "{%0,%1,%2,%3}, {%4,%5,%6,%7}, {%8,%9}, {%0,%1,%2,%3};"
                 : "+f"(c[0]), "+f"(c[1]), "+f"(c[2]), "+f"(c[3])
                 : "r"(a[0]), "r"(a[1]), "r"(a[2]), "r"(a[3]), "r"(b[0]), "r"(b[1]));
}
__device__ __forceinline__ uint32_t pkh2(float a, float b) {
    __half2 t = __floats2half2_rn(a, b);
    return *reinterpret_cast<uint32_t*>(&t);
}
__device__ __forceinline__ unsigned long long pk2(float lo, float hi) {
    unsigned long long r;
    asm("mov.b64 %0, {%1, %2};" : "=l"(r) : "r"(__float_as_uint(lo)), "r"(__float_as_uint(hi)));
    return r;
}
__device__ __forceinline__ void fma2(unsigned long long& d, unsigned long long a, unsigned long long b) {
    asm("fma.rn.f32x2 %0, %1, %2, %3;" : "=l"(d) : "l"(a), "l"(b), "l"(d));
}
__device__ __forceinline__ float gelu_exact(float x) {
    return 0.5f * x * (1.0f + erff(x * 0.7071067811865476f));
}
__device__ __forceinline__ void split_store2(__half* ohi, __half* olo, size_t off, float v0, float v1) {
    __half h0 = __float2half_rn(v0), h1 = __float2half_rn(v1);
    float l0 = v0 - __half2float(h0), l1 = v1 - __half2float(h1);
    *reinterpret_cast<uint32_t*>(ohi + off) = pkh2(__half2float(h0), __half2float(h1));
    *reinterpret_cast<uint32_t*>(olo + off) = pkh2(l0, l1);
}

// ---- conversions ----
__global__ __launch_bounds__(256)
void conv_split(const float* __restrict__ in, __half* __restrict__ hi,
                __half* __restrict__ lo) {
    size_t idx = ((size_t)blockIdx.x * blockDim.x + threadIdx.x) * 8;
    const float4* p = reinterpret_cast<const float4*>(in + idx);
    float4 a = p[0], b = p[1];
    float v[8] = { a.x, a.y, a.z, a.w, b.x, b.y, b.z, b.w };
    float hf[8], lf[8];
    #pragma unroll
    for (int i = 0; i < 8; ++i) {
        __half h = __float2half_rn(v[i]);
        hf[i] = __half2float(h);
        lf[i] = v[i] - hf[i];
    }
    uint4 H = { pkh2(hf[0], hf[1]), pkh2(hf[2], hf[3]), pkh2(hf[4], hf[5]), pkh2(hf[6], hf[7]) };
    uint4 L = { pkh2(lf[0], lf[1]), pkh2(lf[2], lf[3]), pkh2(lf[4], lf[5]), pkh2(lf[6], lf[7]) };
    *reinterpret_cast<uint4*>(hi + idx) = H;
    *reinterpret_cast<uint4*>(lo + idx) = L;
}

__global__ __launch_bounds__(256)
void conv_hi(const float* __restrict__ in, __half* __restrict__ hi) {
    size_t idx = ((size_t)blockIdx.x * blockDim.x + threadIdx.x) * 8;
    const float4* p = reinterpret_cast<const float4*>(in + idx);
    float4 a = p[0], b = p[1];
    uint4 H = { pkh2(a.x, a.y), pkh2(a.z, a.w), pkh2(b.x, b.y), pkh2(b.z, b.w) };
    *reinterpret_cast<uint4*>(hi + idx) = H;
}

// ---- LayerNorm ----
__device__ __forceinline__ void block_reduce2(float& a, float& b) {
    #pragma unroll
    for (int o = 16; o > 0; o >>= 1) {
        a += __shfl_xor_sync(0xFFFFFFFFu, a, o);
        b += __shfl_xor_sync(0xFFFFFFFFu, b, o);
    }
    __shared__ float sa[8], sb[8];
    int w = threadIdx.x >> 5, l = threadIdx.x & 31;
    if (l == 0) { sa[w] = a; sb[w] = b; }
    __syncthreads();
    if (w == 0) {
        a = (l < 8) ? sa[l] : 0.f;
        b = (l < 8) ? sb[l] : 0.f;
        #pragma unroll
        for (int o = 4; o > 0; o >>= 1) {
            a += __shfl_xor_sync(0xFFFFFFFFu, a, o);
            b += __shfl_xor_sync(0xFFFFFFFFu, b, o);
        }
        if (l == 0) { sa[0] = a; sb[0] = b; }
    }
    __syncthreads();
    a = sa[0]; b = sb[0];
}

template <bool RESID, bool SPLIT>
__global__ __launch_bounds__(256)
void ln_kernel(const float* __restrict__ x, const float* __restrict__ w,
               const float* __restrict__ bias, float* __restrict__ out,
               __half* __restrict__ ohi, __half* __restrict__ olo) {
    size_t row = blockIdx.x;
    float4 v = reinterpret_cast<const float4*>(x + row * DQ)[threadIdx.x];
    float s = v.x + v.y + v.z + v.w;
    float s2 = v.x * v.x + v.y * v.y + v.z * v.z + v.w * v.w;
    block_reduce2(s, s2);
    float mean = s * (1.0f / DQ);
    float rs = rsqrtf(s2 * (1.0f / DQ) - mean * mean + 1e-5f);
    float4 wv = reinterpret_cast<const float4*>(w)[threadIdx.x];
    float4 bv = reinterpret_cast<const float4*>(bias)[threadIdx.x];
    float4 o;
    o.x = (v.x - mean) * rs * wv.x + bv.x;
    o.y = (v.y - mean) * rs * wv.y + bv.y;
    o.z = (v.z - mean) * rs * wv.z + bv.z;
    o.w = (v.w - mean) * rs * wv.w + bv.w;
    if (RESID) { o.x += v.x; o.y += v.y; o.z += v.z; o.w += v.w; }
    reinterpret_cast<float4*>(out + row * DQ)[threadIdx.x] = o;
    if (SPLIT) {
        size_t off = row * DQ + 4 * threadIdx.x;
        split_store2(ohi, olo, off, o.x, o.y);
        split_store2(ohi, olo, off + 2, o.z, o.w);
    }
}

// ---- scan: 256 threads, register weights, float2 h reads ----
__global__ __launch_bounds__(256)
void scan_kernel(const float* __restrict__ gate_w, const float* __restrict__ gate_b,
                 const float* __restrict__ state_flow, const float* __restrict__ inj,
                 __half* __restrict__ hhi, __half* __restrict__ hlo) {
    __shared__ __align__(8) float h[SQ];
    __shared__ __align__(8) unsigned long long part[256];
    const int tid = threadIdx.x;
    const int s = tid & 127;
    const int half = tid >> 7;
    const int b = blockIdx.x;

    unsigned long long wv[64];
    #pragma unroll
    for (int j = 0; j < 64; ++j) {
        int k = half * 64 + j;
        wv[j] = pk2(gate_w[s * SQ + k], state_flow[s * SQ + k]);
    }
    float gb = (half == 0) ? gate_b[s] : 0.0f;
    if (half == 0) h[s] = 0.0f;
    __syncthreads();

    const float* injb = inj + (size_t)b * TQ * SQ;
    for (int t = 0; t < TQ; ++t) {
        float injv = (half == 0) ? injb[(size_t)t * SQ + s] : 0.0f;
        unsigned long long acc2 = 0ull;
        const float2* h2 = reinterpret_cast<const float2*>(h + half * 64);
        #pragma unroll
        for (int j = 0; j < 32; ++j) {
            float2 hp = h2[j];
            fma2(acc2, pk2(hp.x, hp.x), wv[2 * j]);
            fma2(acc2, pk2(hp.y, hp.y), wv[2 * j + 1]);
        }
        part[tid] = acc2;
        __syncthreads();
        if (half == 0) {
            float2 p0 = *reinterpret_cast<float2*>(&part[s]);
            float2 p1 = *reinterpret_cast<float2*>(&part[s + 128]);
            float accg = p0.x + p1.x + gb + injv;
            float accf = p0.y + p1.y;
            float hold = h[s];
            float g = 1.0f / (1.0f + expf(-accg));
            float hn = (1.0f - g) * hold + g * accf;
            h[s] = hn;
            size_t off = ((size_t)(b << 10) + t) * SQ + s;
            __half hh = __float2half_rn(hn);
            hhi[off] = hh;
            hlo[off] = __float2half_rn(hn - __half2float(hh));
        }
        __syncthreads();
    }
}

// ---- narrow HMMA GEMM (128x128, 3-term, for inj) ----
#define ROWP 40
#define MATB (128 * ROWP * 2)
#define NGSM 122880

__global__ __launch_bounds__(256, 1)
void gemm_inj(const __half* __restrict__ Ahi, const __half* __restrict__ Alo,
              const __half* __restrict__ Bhi, const __half* __restrict__ Blo,
              float* __restrict__ outf, int K, int N) {
    constexpr int NSTG = 3;
    constexpr int STGB = 4 * MATB;
    extern __shared__ __align__(16) unsigned char dsm[];
    const uint32_t sbase = smem_u32(dsm);
    const int tid = threadIdx.x, lane = tid & 31, wid = tid >> 5;
    const size_t mBase = (size_t)blockIdx.y * 128, nBase = (size_t)blockIdx.x * 128;

    const int lrow = tid >> 1, lchunk = (tid & 1) * 2;
    const size_t aoff = (mBase + lrow) * (size_t)K + lchunk * 8;
    const size_t boff = (nBase + lrow) * (size_t)K + lchunk * 8;
    const uint32_t soff = (uint32_t)(lrow * 80 + lchunk * 16);
    const int ktiles = K / 32;

    auto issue = [&](int st, int kt) {
        uint32_t sb = sbase + (uint32_t)st * STGB;
        size_t k0 = (size_t)kt * 32;
        const __half* pa = Ahi + aoff + k0;
        const __half* pb = Alo + aoff + k0;
        const __half* pc = Bhi + boff + k0;
        const __half* pd = Blo + boff + k0;
        cpa16(sb + soff,            pa);  cpa16(sb + soff + 16,            pa + 8);
        cpa16(sb + MATB + soff,     pb);  cpa16(sb + MATB + soff + 16,     pb + 8);
        cpa16(sb + 2 * MATB + soff, pc);  cpa16(sb + 2 * MATB + soff + 16, pc + 8);
        cpa16(sb + 3 * MATB + soff, pd);  cpa16(sb + 3 * MATB + soff + 16, pd + 8);
        asm volatile("cp.async.commit_group;" ::: "memory");
    };
    for (int s = 0; s < 2; ++s) issue(s, s);

    const int wy = wid >> 2, wx = wid & 3;
    const int m_w = wy * 64, n_w = wx * 32;
    float acc[4][4][4];
    #pragma unroll
    for (int i = 0; i < 4; ++i)
        #pragma unroll
        for (int j = 0; j < 4; ++j)
            #pragma unroll
            for (int e = 0; e < 4; ++e) acc[i][j][e] = 0.0f;

    for (int kt = 0; kt < ktiles; ++kt) {
        if (ktiles - 1 - kt >= 1) wgrp<1>(); else wgrp<0>();
        __syncthreads();
        if (kt + 2 < ktiles) issue((kt + 2) % NSTG, kt + 2);
        const uint32_t sb = sbase + (uint32_t)(kt % NSTG) * STGB;
        const uint32_t sAh = sb, sAl = sb + MATB, sBh = sb + 2 * MATB, sBl = sb + 3 * MATB;
        #pragma unroll
        for (int kk = 0; kk < 2; ++kk) {
            const int kc = kk * 16;
            const int arow = (lane & 15);
            const int acol = kc + ((lane >> 4) << 3);
            const int brow = (lane & 7) + ((lane >> 4) << 3);
            const int bcol = kc + (lane & 8);
            uint32_t ah[4][4], al[4][4], bh[4][2], bl[4][2];
            #pragma unroll
            for (int mf = 0; mf < 4; ++mf) {
                uint32_t a = (uint32_t)((m_w + mf * 16 + arow) * ROWP + acol) * 2;
                ldsm4(ah[mf][0], ah[mf][1], ah[mf][2], ah[mf][3], sAh + a);
                ldsm4(al[mf][0], al[mf][1], al[mf][2], al[mf][3], sAl + a);
            }
            #pragma unroll
            for (int g = 0; g < 2; ++g) {
                uint32_t a = (uint32_t)((n_w + g * 16 + brow) * ROWP + bcol) * 2;
                uint32_t r0, r1, r2, r3;
                ldsm4(r0, r1, r2, r3, sBh + a);
                bh[g * 2][0] = r0; bh[g * 2][1] = r1; bh[g * 2 + 1][0] = r2; bh[g * 2 + 1][1] = r3;
                ldsm4(r0, r1, r2, r3, sBl + a);
                bl[g * 2][0] = r0; bl[g * 2][1] = r1; bl[g * 2 + 1][0] = r2; bl[g * 2 + 1][1] = r3;
            }
            #pragma unroll
            for (int mf = 0; mf < 4; ++mf)
                #pragma unroll
                for (int nf = 0; nf < 4; ++nf) {
                    mma16816(acc[mf][nf], ah[mf], bh[nf]);
                    mma16816(acc[mf][nf], al[mf], bh[nf]);
                    mma16816(acc[mf][nf], ah[mf], bl[nf]);
                }
        }
        __syncthreads();
    }
    #pragma unroll
    for (int mf = 0; mf < 4; ++mf)
        #pragma unroll
        for (int nf = 0; nf < 4; ++nf) {
            size_t r0 = mBase + m_w + mf * 16 + (lane >> 2);
            size_t cc = nBase + n_w + nf * 8 + (lane & 3) * 2;
            float2 s0 = { acc[mf][nf][0], acc[mf][nf][1] };
            float2 s1 = { acc[mf][nf][2], acc[mf][nf][3] };
            *reinterpret_cast<float2*>(outf + r0 * N + cc) = s0;
            *reinterpret_cast<float2*>(outf + (r0 + 8) * N + cc) = s1;
        }
}

// ---- wide HMMA GEMM (128x256), TERMS in {1,2} ----
// EPI: 1 = +ext[M,N], split-store hi/lo
//      2 = +bias, gelu, store hi only
//      3 = +bias, fp32 store
#define W_AB 10240

template <int EPI, int TERMS>
__global__ __launch_bounds__(256, 1)
void gemm_w(const __half* __restrict__ Ahi, const __half* __restrict__ Alo,
            const __half* __restrict__ Bhi,
            const float* __restrict__ ext, float* __restrict__ outf,
            __half* __restrict__ ohi, __half* __restrict__ olo,
            int K, int N) {
    constexpr int NSTG = (TERMS == 2) ? 4 : 5;
    constexpr int STGB = (TERMS == 2) ? 4 * W_AB : 3 * W_AB;
    constexpr uint32_t BOF = (TERMS == 2) ? 2 * W_AB : W_AB;
    extern __shared__ __align__(16) unsigned char dsm[];
    const uint32_t sbase = smem_u32(dsm);
    const int tid = threadIdx.x, lane = tid & 31, wid = tid >> 5;
    const size_t mBase = (size_t)blockIdx.y * 128, nBase = (size_t)blockIdx.x * 256;

    const int lrow = tid >> 1, lchunk = (tid & 1) * 2;
    const size_t aoff  = (mBase + lrow) * (size_t)K + lchunk * 8;
    const size_t boff0 = (nBase + lrow) * (size_t)K + lchunk * 8;
    const size_t boff1 = (nBase + lrow + 128) * (size_t)K + lchunk * 8;
    const uint32_t soff  = (uint32_t)(lrow * 80 + lchunk * 16);
    const uint32_t soff1 = (uint32_t)((lrow + 128) * 80 + lchunk * 16);
    const int ktiles = K / 32;

    auto issue = [&](int st, int kt) {
        uint32_t sb = sbase + (uint32_t)st * STGB;
        size_t k0 = (size_t)kt * 32;
        const __half* pa = Ahi + aoff + k0;
        const __half* pc = Bhi + boff0 + k0;
        const __half* pd = Bhi + boff1 + k0;
        cpa16(sb + soff,        pa);  cpa16(sb + soff + 16,        pa + 8);
        if (TERMS == 2) {
            const __half* pb = Alo + aoff + k0;
            cpa16(sb + W_AB + soff, pb);  cpa16(sb + W_AB + soff + 16, pb + 8);
        }
        cpa16(sb + BOF + soff,  pc);  cpa16(sb + BOF + soff + 16,  pc + 8);
        cpa16(sb + BOF + soff1, pd);  cpa16(sb + BOF + soff1 + 16, pd + 8);
        asm volatile("cp.async.commit_group;" ::: "memory");
    };
    const int npre = ktiles < NSTG - 1 ? ktiles : NSTG - 1;
    for (int s = 0; s < npre; ++s) issue(s, s);

    const int wy = wid >> 2, wx = wid & 3;
    const int m_w = wy * 64, n_w = wx * 64;

    float acc[4][8][4];
    #pragma unroll
    for (int i = 0; i < 4; ++i)
        #pragma unroll
        for (int j = 0; j < 8; ++j)
            #pragma unroll
            for (int e = 0; e < 4; ++e) acc[i][j][e] = 0.0f;

    for (int kt = 0; kt < ktiles; ++kt) {
        const int rem = ktiles - 1 - kt;
        if (NSTG == 5) {
            if (rem >= 3) wgrp<3>(); else if (rem == 2) wgrp<2>();
            else if (rem == 1) wgrp<1>(); else wgrp<0>();
        } else {
            if (rem >= 2) wgrp<2>(); else if (rem == 1) wgrp<1>(); else wgrp<0>();
        }
        __syncthreads();
        if (kt + NSTG - 1 < ktiles) issue((kt + NSTG - 1) % NSTG, kt + NSTG - 1);

        const uint32_t sb = sbase + (uint32_t)(kt % NSTG) * STGB;
        const uint32_t sAh = sb, sAl = sb + W_AB, sBh = sb + BOF;

        #pragma unroll
        for (int kk = 0; kk < 2; ++kk) {
            const int kc = kk * 16;
            const int arow = (lane & 15);
            const int acol = kc + ((lane >> 4) << 3);
            const int brow = (lane & 7) + ((lane >> 4) << 3);
            const int bcol = kc + (lane & 8);
            uint32_t ah[4][4], al[4][4], bh[8][2];
            #pragma unroll
            for (int mf = 0; mf < 4; ++mf) {
                uint32_t a = (uint32_t)((m_w + mf * 16 + arow) * ROWP + acol) * 2;
                ldsm4(ah[mf][0], ah[mf][1], ah[mf][2], ah[mf][3], sAh + a);
                if (TERMS == 2) ldsm4(al[mf][0], al[mf][1], al[mf][2], al[mf][3], sAl + a);
            }
            #pragma unroll
            for (int g = 0; g < 4; ++g) {
                uint32_t a = (uint32_t)((n_w + g * 16 + brow) * ROWP + bcol) * 2;
                uint32_t r0, r1, r2, r3;
                ldsm4(r0, r1, r2, r3, sBh + a);
                bh[g * 2][0] = r0; bh[g * 2][1] = r1; bh[g * 2 + 1][0] = r2; bh[g * 2 + 1][1] = r3;
            }
            #pragma unroll
            for (int mf = 0; mf < 4; ++mf)
                #pragma unroll
                for (int nf = 0; nf < 8; ++nf) {
                    mma16816(acc[mf][nf], ah[mf], bh[nf]);
                    if (TERMS == 2) mma16816(acc[mf][nf], al[mf], bh[nf]);
                }
        }
        __syncthreads();
    }

    #pragma unroll
    for (int mf = 0; mf < 4; ++mf) {
        #pragma unroll
        for (int nf = 0; nf < 8; ++nf) {
            size_t r0 = mBase + m_w + mf * 16 + (lane >> 2);
            size_t cc = nBase + n_w + nf * 8 + (lane & 3) * 2;
            float v0 = acc[mf][nf][0], v1 = acc[mf][nf][1];
            float v2 = acc[mf][nf][2], v3 = acc[mf][nf][3];
            if (EPI == 1) {
                float2 e0 = *reinterpret_cast<const float2*>(ext + r0 * N + cc);
                float2 e1 = *reinterpret_cast<const float2*>(ext + (r0 + 8) * N + cc);
                v0 += e0.x; v1 += e0.y; v2 += e1.x; v3 += e1.y;
            } else {
                float2 bb = *reinterpret_cast<const float2*>(ext + cc);
                v0 += bb.x; v1 += bb.y; v2 += bb.x; v3 += bb.y;
                if (EPI == 2) {
                    v0 = gelu_exact(v0); v1 = gelu_exact(v1);
                    v2 = gelu_exact(v2); v3 = gelu_exact(v3);
                }
            }
            if (EPI == 3) {
                float2 s0 = { v0, v1 }, s1 = { v2, v3 };
                *reinterpret_cast<float2*>(outf + r0 * N + cc) = s0;
                *reinterpret_cast<float2*>(outf + (r0 + 8) * N + cc) = s1;
            } else if (EPI == 2) {
                *reinterpret_cast<uint32_t*>(ohi + r0 * N + cc) = pkh2(v0, v1);
                *reinterpret_cast<uint32_t*>(ohi + (r0 + 8) * N + cc) = pkh2(v2, v3);
            } else {
                split_store2(ohi, olo, r0 * N + cc, v0, v1);
                split_store2(ohi, olo, (r0 + 8) * N + cc, v2, v3);
            }
        }
    }
}

// ---- launch ----
extern "C" void kernel_launch(void* const* d_in, const int* in_sizes, int n_in,
                              void* d_out, int out_size) {
    const float* x          = (const float*)d_in[0];
    const float* ln1_w      = (const float*)d_in[1];
    const float* ln1_b      = (const float*)d_in[2];
    const float* state_flow = (const float*)d_in[3];
    const float* injection  = (const float*)d_in[4];
    const float* readout    = (const float*)d_in[5];
    const float* gate_w     = (const float*)d_in[6];
    const float* gate_b     = (const float*)d_in[7];
    const float* w1         = (const float*)d_in[8];
    const float* b1         = (const float*)d_in[9];
    const float* w2         = (const float*)d_in[10];
    const float* b2         = (const float*)d_in[11];
    const float* ln2_w      = (const float*)d_in[12];
    const float* ln2_b      = (const float*)d_in[13];
    float* out = (float*)d_out;

    float *lnx, *inj, *x3;
    __half *lnxh, *lnxl, *hh, *hl, *x2h, *x2l, *hbh;
    __half *wih, *wil, *roh, *w1h, *w2h;
    cudaGetSymbolAddress((void**)&lnx, g_lnx);
    cudaGetSymbolAddress((void**)&lnxh, g_lnx_hi);
    cudaGetSymbolAddress((void**)&lnxl, g_lnx_lo);
    cudaGetSymbolAddress((void**)&inj, g_inj);
    cudaGetSymbolAddress((void**)&hh, g_h_hi);
    cudaGetSymbolAddress((void**)&hl, g_h_lo);
    cudaGetSymbolAddress((void**)&x2h, g_x2_hi);
    cudaGetSymbolAddress((void**)&x2l, g_x2_lo);
    cudaGetSymbolAddress((void**)&hbh, g_hb_hi);
    cudaGetSymbolAddress((void**)&x3, g_x3);
    cudaGetSymbolAddress((void**)&wih, g_wi_hi);
    cudaGetSymbolAddress((void**)&wil, g_wi_lo);
    cudaGetSymbolAddress((void**)&roh, g_ro_hi);
    cudaGetSymbolAddress((void**)&w1h, g_w1_hi);
    cudaGetSymbolAddress((void**)&w2h, g_w2_hi);

    cudaFuncSetAttribute(gemm_inj, cudaFuncAttributeMaxDynamicSharedMemorySize, NGSM);
    cudaFuncSetAttribute(gemm_w<1, 2>, cudaFuncAttributeMaxDynamicSharedMemorySize, 4 * 4 * W_AB);
    cudaFuncSetAttribute(gemm_w<2, 2>, cudaFuncAttributeMaxDynamicSharedMemorySize, 4 * 4 * W_AB);
    cudaFuncSetAttribute(gemm_w<3, 1>, cudaFuncAttributeMaxDynamicSharedMemorySize, 5 * 3 * W_AB);

    // weight conversions
    conv_split<<<(SQ * DQ / 8) / 256, 256>>>(injection, wih, wil);
    conv_hi<<<(DQ * SQ / 8) / 256, 256>>>(readout, roh);
    conv_hi<<<(int)(((size_t)HQ * DQ / 8) / 256), 256>>>(w1, w1h);
    conv_hi<<<(int)(((size_t)DQ * HQ / 8) / 256), 256>>>(w2, w2h);
    // LN1 (+split)
    ln_kernel<false, true><<<MQ, 256>>>(x, ln1_w, ln1_b, lnx, lnxh, lnxl);
    // inj = lnx @ injection^T   [M x 128], K=1024  (3-term narrow)
    gemm_inj<<<dim3(1, MQ / 128), 256, NGSM>>>(lnxh, lnxl, wih, wil, inj, DQ, SQ);
    // scan -> h hi/lo
    scan_kernel<<<BQ, 256>>>(gate_w, gate_b, state_flow, inj, hh, hl);
    // x2 = lnx + h @ readout^T  [M x 1024], K=128  (2-term, split-store)
    gemm_w<1, 2><<<dim3(DQ / 256, MQ / 128), 256, 4 * 4 * W_AB>>>(
        hh, hl, roh, lnx, nullptr, x2h, x2l, SQ, DQ);
    // hb = gelu(x2 @ w1^T + b1) [M x 4096], K=1024 (2-term, hi-only store)
    gemm_w<2, 2><<<dim3(HQ / 256, MQ / 128), 256, 4 * 4 * W_AB>>>(
        x2h, x2l, w1h, b1, nullptr, hbh, nullptr, DQ, HQ);
    // x3 = hb @ w2^T + b2       [M x 1024], K=4096 (1-term, fp32 store)
    gemm_w<3, 1><<<dim3(DQ / 256, MQ / 128), 256, 5 * 3 * W_AB>>>(
        hbh, nullptr, w2h, b2, x3, nullptr, nullptr, HQ, DQ);
    // out = x3 + LN(x3)
    ln_kernel<true, false><<<MQ, 256>>>(x3, ln2_w, ln2_b, out, nullptr, nullptr);
}

// round 8
// speedup vs baseline: 4.4059x; 1.1954x over previous
#include <cuda_runtime.h>
#include <cuda_fp16.h>
#include <math.h>
#include <stdint.h>

#define BQ 32
#define TQ 1024
#define DQ 1024
#define SQ 128
#define HQ 4096
#define MQ (BQ * TQ)

// ---- scratch (hi/lo fp16 buffers, plain row-major) ----
__device__ __align__(16) float  g_lnx[(size_t)MQ * DQ];
__device__ __align__(16) __half g_lnx_hi[(size_t)MQ * DQ];
__device__ __align__(16) __half g_lnx_lo[(size_t)MQ * DQ];
__device__ __align__(16) float  g_inj[(size_t)MQ * SQ];
__device__ __align__(16) __half g_h_hi[(size_t)MQ * SQ];
__device__ __align__(16) __half g_h_lo[(size_t)MQ * SQ];
__device__ __align__(16) __half g_x2_hi[(size_t)MQ * DQ];
__device__ __align__(16) __half g_hb_hi[(size_t)MQ * HQ];
__device__ __align__(16) float  g_x3[(size_t)MQ * DQ];
__device__ __align__(16) __half g_wi_hi[SQ * DQ], g_wi_lo[SQ * DQ];
__device__ __align__(16) __half g_ro_hi[DQ * SQ];
__device__ __align__(16) __half g_w1_hi[(size_t)HQ * DQ];
__device__ __align__(16) __half g_w2_hi[(size_t)DQ * HQ];

// ---- helpers ----
__device__ __forceinline__ uint32_t smem_u32(const void* p) {
    uint32_t a;
    asm("{ .reg .u64 t; cvta.to.shared.u64 t, %1; cvt.u32.u64 %0, t; }" : "=r"(a) : "l"(p));
    return a;
}
__device__ __forceinline__ void cpa16(uint32_t s, const void* g) {
    asm volatile("cp.async.cg.shared.global [%0], [%1], 16;" :: "r"(s), "l"(g) : "memory");
}
template <int N>
__device__ __forceinline__ void wgrp() {
    asm volatile("cp.async.wait_group %0;" :: "n"(N) : "memory");
}
__device__ __forceinline__ void ldsm4(uint32_t& r0, uint32_t& r1, uint32_t& r2, uint32_t& r3, uint32_t a) {
    asm volatile("ldmatrix.sync.aligned.m8n8.x4.shared.b16 {%0,%1,%2,%3}, [%4];"
                 : "=r"(r0), "=r"(r1), "=r"(r2), "=r"(r3) : "r"(a));
}
__device__ __forceinline__ void mma16816(float* c, const uint32_t* a, const uint32_t* b) {
    asm volatile("mma.sync.aligned.m16n8k16.row.col.f32.f16.f16.f32 "
                 "{%0,%1,%2,%3}, {%4,%5,%6,%7}, {%8,%9}, {%0,%1,%2,%3};"
                 : "+f"(c[0]), "+f"(c[1]), "+f"(c[2]), "+f"(c[3])
                 : "r"(a[0]), "r"(a[1]), "r"(a[2]), "r"(a[3]), "r"(b[0]), "r"(b[1]));
}
__device__ __forceinline__ uint32_t pkh2(float a, float b) {
    __half2 t = __floats2half2_rn(a, b);
    return *reinterpret_cast<uint32_t*>(&t);
}
__device__ __forceinline__ unsigned long long pk2(float lo, float hi) {
    unsigned long long r;
    asm("mov.b64 %0, {%1, %2};" : "=l"(r) : "r"(__float_as_uint(lo)), "r"(__float_as_uint(hi)));
    return r;
}
__device__ __forceinline__ void fma2(unsigned long long& d, unsigned long long a, unsigned long long b) {
    asm("fma.rn.f32x2 %0, %1, %2, %3;" : "=l"(d) : "l"(a), "l"(b), "l"(d));
}
__device__ __forceinline__ float gelu_exact(float x) {
    return 0.5f * x * (1.0f + erff(x * 0.7071067811865476f));
}
__device__ __forceinline__ void split_store2(__half* ohi, __half* olo, size_t off, float v0, float v1) {
    __half h0 = __float2half_rn(v0), h1 = __float2half_rn(v1);
    float l0 = v0 - __half2float(h0), l1 = v1 - __half2float(h1);
    *reinterpret_cast<uint32_t*>(ohi + off) = pkh2(__half2float(h0), __half2float(h1));
    *reinterpret_cast<uint32_t*>(olo + off) = pkh2(l0, l1);
}

// ---- conversions ----
__global__ __launch_bounds__(256)
void conv_split(const float* __restrict__ in, __half* __restrict__ hi,
                __half* __restrict__ lo) {
    size_t idx = ((size_t)blockIdx.x * blockDim.x + threadIdx.x) * 8;
    const float4* p = reinterpret_cast<const float4*>(in + idx);
    float4 a = p[0], b = p[1];
    float v[8] = { a.x, a.y, a.z, a.w, b.x, b.y, b.z, b.w };
    float hf[8], lf[8];
    #pragma unroll
    for (int i = 0; i < 8; ++i) {
        __half h = __float2half_rn(v[i]);
        hf[i] = __half2float(h);
        lf[i] = v[i] - hf[i];
    }
    uint4 H = { pkh2(hf[0], hf[1]), pkh2(hf[2], hf[3]), pkh2(hf[4], hf[5]), pkh2(hf[6], hf[7]) };
    uint4 L = { pkh2(lf[0], lf[1]), pkh2(lf[2], lf[3]), pkh2(lf[4], lf[5]), pkh2(lf[6], lf[7]) };
    *reinterpret_cast<uint4*>(hi + idx) = H;
    *reinterpret_cast<uint4*>(lo + idx) = L;
}

__global__ __launch_bounds__(256)
void conv_hi(const float* __restrict__ in, __half* __restrict__ hi) {
    size_t idx = ((size_t)blockIdx.x * blockDim.x + threadIdx.x) * 8;
    const float4* p = reinterpret_cast<const float4*>(in + idx);
    float4 a = p[0], b = p[1];
    uint4 H = { pkh2(a.x, a.y), pkh2(a.z, a.w), pkh2(b.x, b.y), pkh2(b.z, b.w) };
    *reinterpret_cast<uint4*>(hi + idx) = H;
}

// ---- LayerNorm ----
__device__ __forceinline__ void block_reduce2(float& a, float& b) {
    #pragma unroll
    for (int o = 16; o > 0; o >>= 1) {
        a += __shfl_xor_sync(0xFFFFFFFFu, a, o);
        b += __shfl_xor_sync(0xFFFFFFFFu, b, o);
    }
    __shared__ float sa[8], sb[8];
    int w = threadIdx.x >> 5, l = threadIdx.x & 31;
    if (l == 0) { sa[w] = a; sb[w] = b; }
    __syncthreads();
    if (w == 0) {
        a = (l < 8) ? sa[l] : 0.f;
        b = (l < 8) ? sb[l] : 0.f;
        #pragma unroll
        for (int o = 4; o > 0; o >>= 1) {
            a += __shfl_xor_sync(0xFFFFFFFFu, a, o);
            b += __shfl_xor_sync(0xFFFFFFFFu, b, o);
        }
        if (l == 0) { sa[0] = a; sb[0] = b; }
    }
    __syncthreads();
    a = sa[0]; b = sb[0];
}

template <bool RESID, bool SPLIT>
__global__ __launch_bounds__(256)
void ln_kernel(const float* __restrict__ x, const float* __restrict__ w,
               const float* __restrict__ bias, float* __restrict__ out,
               __half* __restrict__ ohi, __half* __restrict__ olo) {
    size_t row = blockIdx.x;
    float4 v = reinterpret_cast<const float4*>(x + row * DQ)[threadIdx.x];
    float s = v.x + v.y + v.z + v.w;
    float s2 = v.x * v.x + v.y * v.y + v.z * v.z + v.w * v.w;
    block_reduce2(s, s2);
    float mean = s * (1.0f / DQ);
    float rs = rsqrtf(s2 * (1.0f / DQ) - mean * mean + 1e-5f);
    float4 wv = reinterpret_cast<const float4*>(w)[threadIdx.x];
    float4 bv = reinterpret_cast<const float4*>(bias)[threadIdx.x];
    float4 o;
    o.x = (v.x - mean) * rs * wv.x + bv.x;
    o.y = (v.y - mean) * rs * wv.y + bv.y;
    o.z = (v.z - mean) * rs * wv.z + bv.z;
    o.w = (v.w - mean) * rs * wv.w + bv.w;
    if (RESID) { o.x += v.x; o.y += v.y; o.z += v.z; o.w += v.w; }
    reinterpret_cast<float4*>(out + row * DQ)[threadIdx.x] = o;
    if (SPLIT) {
        size_t off = row * DQ + 4 * threadIdx.x;
        split_store2(ohi, olo, off, o.x, o.y);
        split_store2(ohi, olo, off + 2, o.z, o.w);
    }
}

// ---- scan: 256 threads, register weights, float2 h reads ----
__global__ __launch_bounds__(256)
void scan_kernel(const float* __restrict__ gate_w, const float* __restrict__ gate_b,
                 const float* __restrict__ state_flow, const float* __restrict__ inj,
                 __half* __restrict__ hhi, __half* __restrict__ hlo) {
    __shared__ __align__(8) float h[SQ];
    __shared__ __align__(8) unsigned long long part[256];
    const int tid = threadIdx.x;
    const int s = tid & 127;
    const int half = tid >> 7;
    const int b = blockIdx.x;

    unsigned long long wv[64];
    #pragma unroll
    for (int j = 0; j < 64; ++j) {
        int k = half * 64 + j;
        wv[j] = pk2(gate_w[s * SQ + k], state_flow[s * SQ + k]);
    }
    float gb = (half == 0) ? gate_b[s] : 0.0f;
    if (half == 0) h[s] = 0.0f;
    __syncthreads();

    const float* injb = inj + (size_t)b * TQ * SQ;
    for (int t = 0; t < TQ; ++t) {
        float injv = (half == 0) ? injb[(size_t)t * SQ + s] : 0.0f;
        unsigned long long acc2 = 0ull;
        const float2* h2 = reinterpret_cast<const float2*>(h + half * 64);
        #pragma unroll
        for (int j = 0; j < 32; ++j) {
            float2 hp = h2[j];
            fma2(acc2, pk2(hp.x, hp.x), wv[2 * j]);
            fma2(acc2, pk2(hp.y, hp.y), wv[2 * j + 1]);
        }
        part[tid] = acc2;
        __syncthreads();
        if (half == 0) {
            float2 p0 = *reinterpret_cast<float2*>(&part[s]);
            float2 p1 = *reinterpret_cast<float2*>(&part[s + 128]);
            float accg = p0.x + p1.x + gb + injv;
            float accf = p0.y + p1.y;
            float hold = h[s];
            float g = 1.0f / (1.0f + expf(-accg));
            float hn = (1.0f - g) * hold + g * accf;
            h[s] = hn;
            size_t off = ((size_t)(b << 10) + t) * SQ + s;
            __half hh = __float2half_rn(hn);
            hhi[off] = hh;
            hlo[off] = __float2half_rn(hn - __half2float(hh));
        }
        __syncthreads();
    }
}

// ---- narrow HMMA GEMM (128x128, 3-term, for inj) ----
#define ROWP 40
#define MATB (128 * ROWP * 2)
#define NGSM 122880

__global__ __launch_bounds__(256, 1)
void gemm_inj(const __half* __restrict__ Ahi, const __half* __restrict__ Alo,
              const __half* __restrict__ Bhi, const __half* __restrict__ Blo,
              float* __restrict__ outf, int K, int N) {
    constexpr int NSTG = 3;
    constexpr int STGB = 4 * MATB;
    extern __shared__ __align__(16) unsigned char dsm[];
    const uint32_t sbase = smem_u32(dsm);
    const int tid = threadIdx.x, lane = tid & 31, wid = tid >> 5;
    const size_t mBase = (size_t)blockIdx.y * 128, nBase = (size_t)blockIdx.x * 128;

    const int lrow = tid >> 1, lchunk = (tid & 1) * 2;
    const size_t aoff = (mBase + lrow) * (size_t)K + lchunk * 8;
    const size_t boff = (nBase + lrow) * (size_t)K + lchunk * 8;
    const uint32_t soff = (uint32_t)(lrow * 80 + lchunk * 16);
    const int ktiles = K / 32;

    auto issue = [&](int st, int kt) {
        uint32_t sb = sbase + (uint32_t)st * STGB;
        size_t k0 = (size_t)kt * 32;
        const __half* pa = Ahi + aoff + k0;
        const __half* pb = Alo + aoff + k0;
        const __half* pc = Bhi + boff + k0;
        const __half* pd = Blo + boff + k0;
        cpa16(sb + soff,            pa);  cpa16(sb + soff + 16,            pa + 8);
        cpa16(sb + MATB + soff,     pb);  cpa16(sb + MATB + soff + 16,     pb + 8);
        cpa16(sb + 2 * MATB + soff, pc);  cpa16(sb + 2 * MATB + soff + 16, pc + 8);
        cpa16(sb + 3 * MATB + soff, pd);  cpa16(sb + 3 * MATB + soff + 16, pd + 8);
        asm volatile("cp.async.commit_group;" ::: "memory");
    };
    for (int s = 0; s < 2; ++s) issue(s, s);

    const int wy = wid >> 2, wx = wid & 3;
    const int m_w = wy * 64, n_w = wx * 32;
    float acc[4][4][4];
    #pragma unroll
    for (int i = 0; i < 4; ++i)
        #pragma unroll
        for (int j = 0; j < 4; ++j)
            #pragma unroll
            for (int e = 0; e < 4; ++e) acc[i][j][e] = 0.0f;

    for (int kt = 0; kt < ktiles; ++kt) {
        if (ktiles - 1 - kt >= 1) wgrp<1>(); else wgrp<0>();
        __syncthreads();
        if (kt + 2 < ktiles) issue((kt + 2) % NSTG, kt + 2);
        const uint32_t sb = sbase + (uint32_t)(kt % NSTG) * STGB;
        const uint32_t sAh = sb, sAl = sb + MATB, sBh = sb + 2 * MATB, sBl = sb + 3 * MATB;
        #pragma unroll
        for (int kk = 0; kk < 2; ++kk) {
            const int kc = kk * 16;
            const int arow = (lane & 15);
            const int acol = kc + ((lane >> 4) << 3);
            const int brow = (lane & 7) + ((lane >> 4) << 3);
            const int bcol = kc + (lane & 8);
            uint32_t ah[4][4], al[4][4], bh[4][2], bl[4][2];
            #pragma unroll
            for (int mf = 0; mf < 4; ++mf) {
                uint32_t a = (uint32_t)((m_w + mf * 16 + arow) * ROWP + acol) * 2;
                ldsm4(ah[mf][0], ah[mf][1], ah[mf][2], ah[mf][3], sAh + a);
                ldsm4(al[mf][0], al[mf][1], al[mf][2], al[mf][3], sAl + a);
            }
            #pragma unroll
            for (int g = 0; g < 2; ++g) {
                uint32_t a = (uint32_t)((n_w + g * 16 + brow) * ROWP + bcol) * 2;
                uint32_t r0, r1, r2, r3;
                ldsm4(r0, r1, r2, r3, sBh + a);
                bh[g * 2][0] = r0; bh[g * 2][1] = r1; bh[g * 2 + 1][0] = r2; bh[g * 2 + 1][1] = r3;
                ldsm4(r0, r1, r2, r3, sBl + a);
                bl[g * 2][0] = r0; bl[g * 2][1] = r1; bl[g * 2 + 1][0] = r2; bl[g * 2 + 1][1] = r3;
            }
            #pragma unroll
            for (int mf = 0; mf < 4; ++mf)
                #pragma unroll
                for (int nf = 0; nf < 4; ++nf) {
                    mma16816(acc[mf][nf], ah[mf], bh[nf]);
                    mma16816(acc[mf][nf], al[mf], bh[nf]);
                    mma16816(acc[mf][nf], ah[mf], bl[nf]);
                }
        }
        __syncthreads();
    }
    #pragma unroll
    for (int mf = 0; mf < 4; ++mf)
        #pragma unroll
        for (int nf = 0; nf < 4; ++nf) {
            size_t r0 = mBase + m_w + mf * 16 + (lane >> 2);
            size_t cc = nBase + n_w + nf * 8 + (lane & 3) * 2;
            float2 s0 = { acc[mf][nf][0], acc[mf][nf][1] };
            float2 s1 = { acc[mf][nf][2], acc[mf][nf][3] };
            *reinterpret_cast<float2*>(outf + r0 * N + cc) = s0;
            *reinterpret_cast<float2*>(outf + (r0 + 8) * N + cc) = s1;
        }
}

// ---- wide HMMA GEMM (128x256), TERMS in {1,2} ----
// EPI: 2 = +bias, gelu, store hi only
//      3 = +bias, fp32 store
//      4 = +ext[M,N], store hi only
#define W_AB 10240

template <int EPI, int TERMS>
__global__ __launch_bounds__(256, 1)
void gemm_w(const __half* __restrict__ Ahi, const __half* __restrict__ Alo,
            const __half* __restrict__ Bhi,
            const float* __restrict__ ext, float* __restrict__ outf,
            __half* __restrict__ ohi, int K, int N) {
    constexpr int NSTG = (TERMS == 2) ? 4 : 5;
    constexpr int STGB = (TERMS == 2) ? 4 * W_AB : 3 * W_AB;
    constexpr uint32_t BOF = (TERMS == 2) ? 2 * W_AB : W_AB;
    extern __shared__ __align__(16) unsigned char dsm[];
    const uint32_t sbase = smem_u32(dsm);
    const int tid = threadIdx.x, lane = tid & 31, wid = tid >> 5;
    const size_t mBase = (size_t)blockIdx.y * 128, nBase = (size_t)blockIdx.x * 256;

    const int lrow = tid >> 1, lchunk = (tid & 1) * 2;
    const size_t aoff  = (mBase + lrow) * (size_t)K + lchunk * 8;
    const size_t boff0 = (nBase + lrow) * (size_t)K + lchunk * 8;
    const size_t boff1 = (nBase + lrow + 128) * (size_t)K + lchunk * 8;
    const uint32_t soff  = (uint32_t)(lrow * 80 + lchunk * 16);
    const uint32_t soff1 = (uint32_t)((lrow + 128) * 80 + lchunk * 16);
    const int ktiles = K / 32;

    auto issue = [&](int st, int kt) {
        uint32_t sb = sbase + (uint32_t)st * STGB;
        size_t k0 = (size_t)kt * 32;
        const __half* pa = Ahi + aoff + k0;
        const __half* pc = Bhi + boff0 + k0;
        const __half* pd = Bhi + boff1 + k0;
        cpa16(sb + soff,        pa);  cpa16(sb + soff + 16,        pa + 8);
        if (TERMS == 2) {
            const __half* pb = Alo + aoff + k0;
            cpa16(sb + W_AB + soff, pb);  cpa16(sb + W_AB + soff + 16, pb + 8);
        }
        cpa16(sb + BOF + soff,  pc);  cpa16(sb + BOF + soff + 16,  pc + 8);
        cpa16(sb + BOF + soff1, pd);  cpa16(sb + BOF + soff1 + 16, pd + 8);
        asm volatile("cp.async.commit_group;" ::: "memory");
    };
    const int npre = ktiles < NSTG - 1 ? ktiles : NSTG - 1;
    for (int s = 0; s < npre; ++s) issue(s, s);

    const int wy = wid >> 2, wx = wid & 3;
    const int m_w = wy * 64, n_w = wx * 64;

    float acc[4][8][4];
    #pragma unroll
    for (int i = 0; i < 4; ++i)
        #pragma unroll
        for (int j = 0; j < 8; ++j)
            #pragma unroll
            for (int e = 0; e < 4; ++e) acc[i][j][e] = 0.0f;

    for (int kt = 0; kt < ktiles; ++kt) {
        const int rem = ktiles - 1 - kt;
        if (NSTG == 5) {
            if (rem >= 3) wgrp<3>(); else if (rem == 2) wgrp<2>();
            else if (rem == 1) wgrp<1>(); else wgrp<0>();
        } else {
            if (rem >= 2) wgrp<2>(); else if (rem == 1) wgrp<1>(); else wgrp<0>();
        }
        __syncthreads();
        if (kt + NSTG - 1 < ktiles) issue((kt + NSTG - 1) % NSTG, kt + NSTG - 1);

        const uint32_t sb = sbase + (uint32_t)(kt % NSTG) * STGB;
        const uint32_t sAh = sb, sAl = sb + W_AB, sBh = sb + BOF;

        #pragma unroll
        for (int kk = 0; kk < 2; ++kk) {
            const int kc = kk * 16;
            const int arow = (lane & 15);
            const int acol = kc + ((lane >> 4) << 3);
            const int brow = (lane & 7) + ((lane >> 4) << 3);
            const int bcol = kc + (lane & 8);
            uint32_t ah[4][4], al[4][4], bh[8][2];
            #pragma unroll
            for (int mf = 0; mf < 4; ++mf) {
                uint32_t a = (uint32_t)((m_w + mf * 16 + arow) * ROWP + acol) * 2;
                ldsm4(ah[mf][0], ah[mf][1], ah[mf][2], ah[mf][3], sAh + a);
                if (TERMS == 2) ldsm4(al[mf][0], al[mf][1], al[mf][2], al[mf][3], sAl + a);
            }
            #pragma unroll
            for (int g = 0; g < 4; ++g) {
                uint32_t a = (uint32_t)((n_w + g * 16 + brow) * ROWP + bcol) * 2;
                uint32_t r0, r1, r2, r3;
                ldsm4(r0, r1, r2, r3, sBh + a);
                bh[g * 2][0] = r0; bh[g * 2][1] = r1; bh[g * 2 + 1][0] = r2; bh[g * 2 + 1][1] = r3;
            }
            #pragma unroll
            for (int mf = 0; mf < 4; ++mf)
                #pragma unroll
                for (int nf = 0; nf < 8; ++nf) {
                    mma16816(acc[mf][nf], ah[mf], bh[nf]);
                    if (TERMS == 2) mma16816(acc[mf][nf], al[mf], bh[nf]);
                }
        }
        __syncthreads();
    }

    #pragma unroll
    for (int mf = 0; mf < 4; ++mf) {
        #pragma unroll
        for (int nf = 0; nf < 8; ++nf) {
            size_t r0 = mBase + m_w + mf * 16 + (lane >> 2);
            size_t cc = nBase + n_w + nf * 8 + (lane & 3) * 2;
            float v0 = acc[mf][nf][0], v1 = acc[mf][nf][1];
            float v2 = acc[mf][nf][2], v3 = acc[mf][nf][3];
            if (EPI == 4) {
                float2 e0 = *reinterpret_cast<const float2*>(ext + r0 * N + cc);
                float2 e1 = *reinterpret_cast<const float2*>(ext + (r0 + 8) * N + cc);
                v0 += e0.x; v1 += e0.y; v2 += e1.x; v3 += e1.y;
            } else {
                float2 bb = *reinterpret_cast<const float2*>(ext + cc);
                v0 += bb.x; v1 += bb.y; v2 += bb.x; v3 += bb.y;
                if (EPI == 2) {
                    v0 = gelu_exact(v0); v1 = gelu_exact(v1);
                    v2 = gelu_exact(v2); v3 = gelu_exact(v3);
                }
            }
            if (EPI == 3) {
                float2 s0 = { v0, v1 }, s1 = { v2, v3 };
                *reinterpret_cast<float2*>(outf + r0 * N + cc) = s0;
                *reinterpret_cast<float2*>(outf + (r0 + 8) * N + cc) = s1;
            } else {
                *reinterpret_cast<uint32_t*>(ohi + r0 * N + cc) = pkh2(v0, v1);
                *reinterpret_cast<uint32_t*>(ohi + (r0 + 8) * N + cc) = pkh2(v2, v3);
            }
        }
    }
}

// ---- launch ----
extern "C" void kernel_launch(void* const* d_in, const int* in_sizes, int n_in,
                              void* d_out, int out_size) {
    const float* x          = (const float*)d_in[0];
    const float* ln1_w      = (const float*)d_in[1];
    const float* ln1_b      = (const float*)d_in[2];
    const float* state_flow = (const float*)d_in[3];
    const float* injection  = (const float*)d_in[4];
    const float* readout    = (const float*)d_in[5];
    const float* gate_w     = (const float*)d_in[6];
    const float* gate_b     = (const float*)d_in[7];
    const float* w1         = (const float*)d_in[8];
    const float* b1         = (const float*)d_in[9];
    const float* w2         = (const float*)d_in[10];
    const float* b2         = (const float*)d_in[11];
    const float* ln2_w      = (const float*)d_in[12];
    const float* ln2_b      = (const float*)d_in[13];
    float* out = (float*)d_out;

    float *lnx, *inj, *x3;
    __half *lnxh, *lnxl, *hh, *hl, *x2h, *hbh;
    __half *wih, *wil, *roh, *w1h, *w2h;
    cudaGetSymbolAddress((void**)&lnx, g_lnx);
    cudaGetSymbolAddress((void**)&lnxh, g_lnx_hi);
    cudaGetSymbolAddress((void**)&lnxl, g_lnx_lo);
    cudaGetSymbolAddress((void**)&inj, g_inj);
    cudaGetSymbolAddress((void**)&hh, g_h_hi);
    cudaGetSymbolAddress((void**)&hl, g_h_lo);
    cudaGetSymbolAddress((void**)&x2h, g_x2_hi);
    cudaGetSymbolAddress((void**)&hbh, g_hb_hi);
    cudaGetSymbolAddress((void**)&x3, g_x3);
    cudaGetSymbolAddress((void**)&wih, g_wi_hi);
    cudaGetSymbolAddress((void**)&wil, g_wi_lo);
    cudaGetSymbolAddress((void**)&roh, g_ro_hi);
    cudaGetSymbolAddress((void**)&w1h, g_w1_hi);
    cudaGetSymbolAddress((void**)&w2h, g_w2_hi);

    cudaFuncSetAttribute(gemm_inj, cudaFuncAttributeMaxDynamicSharedMemorySize, NGSM);
    cudaFuncSetAttribute(gemm_w<4, 2>, cudaFuncAttributeMaxDynamicSharedMemorySize, 4 * 4 * W_AB);
    cudaFuncSetAttribute(gemm_w<2, 1>, cudaFuncAttributeMaxDynamicSharedMemorySize, 5 * 3 * W_AB);
    cudaFuncSetAttribute(gemm_w<3, 1>, cudaFuncAttributeMaxDynamicSharedMemorySize, 5 * 3 * W_AB);

    // weight conversions
    conv_split<<<(SQ * DQ / 8) / 256, 256>>>(injection, wih, wil);
    conv_hi<<<(DQ * SQ / 8) / 256, 256>>>(readout, roh);
    conv_hi<<<(int)(((size_t)HQ * DQ / 8) / 256), 256>>>(w1, w1h);
    conv_hi<<<(int)(((size_t)DQ * HQ / 8) / 256), 256>>>(w2, w2h);
    // LN1 (+split)
    ln_kernel<false, true><<<MQ, 256>>>(x, ln1_w, ln1_b, lnx, lnxh, lnxl);
    // inj = lnx @ injection^T   [M x 128], K=1024  (3-term narrow)
    gemm_inj<<<dim3(1, MQ / 128), 256, NGSM>>>(lnxh, lnxl, wih, wil, inj, DQ, SQ);
    // scan -> h hi/lo
    scan_kernel<<<BQ, 256>>>(gate_w, gate_b, state_flow, inj, hh, hl);
    // x2 = lnx + h @ readout^T  [M x 1024], K=128  (2-term, hi-only store)
    gemm_w<4, 2><<<dim3(DQ / 256, MQ / 128), 256, 4 * 4 * W_AB>>>(
        hh, hl, roh, lnx, nullptr, x2h, SQ, DQ);
    // hb = gelu(x2 @ w1^T + b1) [M x 4096], K=1024 (1-term, hi-only store)
    gemm_w<2, 1><<<dim3(HQ / 256, MQ / 128), 256, 5 * 3 * W_AB>>>(
        x2h, nullptr, w1h, b1, nullptr, hbh, DQ, HQ);
    // x3 = hb @ w2^T + b2       [M x 1024], K=4096 (1-term, fp32 store)
    gemm_w<3, 1><<<dim3(DQ / 256, MQ / 128), 256, 5 * 3 * W_AB>>>(
        hbh, nullptr, w2h, b2, x3, nullptr, HQ, DQ);
    // out = x3 + LN(x3)
    ln_kernel<true, false><<<MQ, 256>>>(x3, ln2_w, ln2_b, out, nullptr, nullptr);
}

// round 9
// speedup vs baseline: 4.6894x; 1.0644x over previous
#include <cuda_runtime.h>
#include <cuda_fp16.h>
#include <math.h>
#include <stdint.h>

#define BQ 32
#define TQ 1024
#define DQ 1024
#define SQ 128
#define HQ 4096
#define MQ (BQ * TQ)

// ---- scratch ----
__device__ __align__(16) __half g_lnx_hi[(size_t)MQ * DQ];
__device__ __align__(16) __half g_lnx_lo[(size_t)MQ * DQ];
__device__ __align__(16) float  g_inj[(size_t)MQ * SQ];
__device__ __align__(16) __half g_h_hi[(size_t)MQ * SQ];
__device__ __align__(16) __half g_h_lo[(size_t)MQ * SQ];
__device__ __align__(16) __half g_x2_hi[(size_t)MQ * DQ];
__device__ __align__(16) __half g_hb_hi[(size_t)MQ * HQ];
__device__ __align__(16) float  g_x3[(size_t)MQ * DQ];
__device__ __align__(16) __half g_wi_hi[SQ * DQ], g_wi_lo[SQ * DQ];
__device__ __align__(16) __half g_ro_hi[DQ * SQ];
__device__ __align__(16) __half g_w1_hi[(size_t)HQ * DQ];
__device__ __align__(16) __half g_w2_hi[(size_t)DQ * HQ];

// ---- helpers ----
__device__ __forceinline__ uint32_t smem_u32(const void* p) {
    uint32_t a;
    asm("{ .reg .u64 t; cvta.to.shared.u64 t, %1; cvt.u32.u64 %0, t; }" : "=r"(a) : "l"(p));
    return a;
}
__device__ __forceinline__ void cpa16(uint32_t s, const void* g) {
    asm volatile("cp.async.cg.shared.global [%0], [%1], 16;" :: "r"(s), "l"(g) : "memory");
}
template <int N>
__device__ __forceinline__ void wgrp() {
    asm volatile("cp.async.wait_group %0;" :: "n"(N) : "memory");
}
__device__ __forceinline__ void ldsm4(uint32_t& r0, uint32_t& r1, uint32_t& r2, uint32_t& r3, uint32_t a) {
    asm volatile("ldmatrix.sync.aligned.m8n8.x4.shared.b16 {%0,%1,%2,%3}, [%4];"
                 : "=r"(r0), "=r"(r1), "=r"(r2), "=r"(r3) : "r"(a));
}
__device__ __forceinline__ void mma16816(float* c, const uint32_t* a, const uint32_t* b) {
    asm volatile("mma.sync.aligned.m16n8k16.row.col.f32.f16.f16.f32 "
                 "{%0,%1,%2,%3}, {%4,%5,%6,%7}, {%8,%9}, {%0,%1,%2,%3};"
                 : "+f"(c[0]), "+f"(c[1]), "+f"(c[2]), "+f"(c[3])
                 : "r"(a[0]), "r"(a[1]), "r"(a[2]), "r"(a[3]), "r"(b[0]), "r"(b[1]));
}
__device__ __forceinline__ uint32_t pkh2(float a, float b) {
    __half2 t = __floats2half2_rn(a, b);
    return *reinterpret_cast<uint32_t*>(&t);
}
__device__ __forceinline__ unsigned long long pk2(float lo, float hi) {
    unsigned long long r;
    asm("mov.b64 %0, {%1, %2};" : "=l"(r) : "r"(__float_as_uint(lo)), "r"(__float_as_uint(hi)));
    return r;
}
__device__ __forceinline__ void fma2(unsigned long long& d, unsigned long long a, unsigned long long b) {
    asm("fma.rn.f32x2 %0, %1, %2, %3;" : "=l"(d) : "l"(a), "l"(b), "l"(d));
}
__device__ __forceinline__ float gelu_exact(float x) {
    return 0.5f * x * (1.0f + erff(x * 0.7071067811865476f));
}
__device__ __forceinline__ void split_store2(__half* ohi, __half* olo, size_t off, float v0, float v1) {
    __half h0 = __float2half_rn(v0), h1 = __float2half_rn(v1);
    float l0 = v0 - __half2float(h0), l1 = v1 - __half2float(h1);
    *reinterpret_cast<uint32_t*>(ohi + off) = pkh2(__half2float(h0), __half2float(h1));
    *reinterpret_cast<uint32_t*>(olo + off) = pkh2(l0, l1);
}
__device__ __forceinline__ float2 unpkh2(uint32_t u) {
    __half2 h = *reinterpret_cast<__half2*>(&u);
    return __half22float2(h);
}

// ---- conversions ----
__global__ __launch_bounds__(256)
void conv_split(const float* __restrict__ in, __half* __restrict__ hi,
                __half* __restrict__ lo) {
    size_t idx = ((size_t)blockIdx.x * blockDim.x + threadIdx.x) * 8;
    const float4* p = reinterpret_cast<const float4*>(in + idx);
    float4 a = p[0], b = p[1];
    float v[8] = { a.x, a.y, a.z, a.w, b.x, b.y, b.z, b.w };
    float hf[8], lf[8];
    #pragma unroll
    for (int i = 0; i < 8; ++i) {
        __half h = __float2half_rn(v[i]);
        hf[i] = __half2float(h);
        lf[i] = v[i] - hf[i];
    }
    uint4 H = { pkh2(hf[0], hf[1]), pkh2(hf[2], hf[3]), pkh2(hf[4], hf[5]), pkh2(hf[6], hf[7]) };
    uint4 L = { pkh2(lf[0], lf[1]), pkh2(lf[2], lf[3]), pkh2(lf[4], lf[5]), pkh2(lf[6], lf[7]) };
    *reinterpret_cast<uint4*>(hi + idx) = H;
    *reinterpret_cast<uint4*>(lo + idx) = L;
}

__global__ __launch_bounds__(256)
void conv_hi(const float* __restrict__ in, __half* __restrict__ hi) {
    size_t idx = ((size_t)blockIdx.x * blockDim.x + threadIdx.x) * 8;
    const float4* p = reinterpret_cast<const float4*>(in + idx);
    float4 a = p[0], b = p[1];
    uint4 H = { pkh2(a.x, a.y), pkh2(a.z, a.w), pkh2(b.x, b.y), pkh2(b.z, b.w) };
    *reinterpret_cast<uint4*>(hi + idx) = H;
}

// ---- LayerNorm ----
__device__ __forceinline__ void block_reduce2(float& a, float& b) {
    #pragma unroll
    for (int o = 16; o > 0; o >>= 1) {
        a += __shfl_xor_sync(0xFFFFFFFFu, a, o);
        b += __shfl_xor_sync(0xFFFFFFFFu, b, o);
    }
    __shared__ float sa[8], sb[8];
    int w = threadIdx.x >> 5, l = threadIdx.x & 31;
    if (l == 0) { sa[w] = a; sb[w] = b; }
    __syncthreads();
    if (w == 0) {
        a = (l < 8) ? sa[l] : 0.f;
        b = (l < 8) ? sb[l] : 0.f;
        #pragma unroll
        for (int o = 4; o > 0; o >>= 1) {
            a += __shfl_xor_sync(0xFFFFFFFFu, a, o);
            b += __shfl_xor_sync(0xFFFFFFFFu, b, o);
        }
        if (l == 0) { sa[0] = a; sb[0] = b; }
    }
    __syncthreads();
    a = sa[0]; b = sb[0];
}

template <bool RESID, bool SPLIT, bool WF32>
__global__ __launch_bounds__(256)
void ln_kernel(const float* __restrict__ x, const float* __restrict__ w,
               const float* __restrict__ bias, float* __restrict__ out,
               __half* __restrict__ ohi, __half* __restrict__ olo) {
    size_t row = blockIdx.x;
    float4 v = reinterpret_cast<const float4*>(x + row * DQ)[threadIdx.x];
    float s = v.x + v.y + v.z + v.w;
    float s2 = v.x * v.x + v.y * v.y + v.z * v.z + v.w * v.w;
    block_reduce2(s, s2);
    float mean = s * (1.0f / DQ);
    float rs = rsqrtf(s2 * (1.0f / DQ) - mean * mean + 1e-5f);
    float4 wv = reinterpret_cast<const float4*>(w)[threadIdx.x];
    float4 bv = reinterpret_cast<const float4*>(bias)[threadIdx.x];
    float4 o;
    o.x = (v.x - mean) * rs * wv.x + bv.x;
    o.y = (v.y - mean) * rs * wv.y + bv.y;
    o.z = (v.z - mean) * rs * wv.z + bv.z;
    o.w = (v.w - mean) * rs * wv.w + bv.w;
    if (RESID) { o.x += v.x; o.y += v.y; o.z += v.z; o.w += v.w; }
    if (WF32) reinterpret_cast<float4*>(out + row * DQ)[threadIdx.x] = o;
    if (SPLIT) {
        size_t off = row * DQ + 4 * threadIdx.x;
        split_store2(ohi, olo, off, o.x, o.y);
        split_store2(ohi, olo, off + 2, o.z, o.w);
    }
}

// ---- scan: 512 threads, 4-way k split, register weights ----
__global__ __launch_bounds__(512)
void scan_kernel(const float* __restrict__ gate_w, const float* __restrict__ gate_b,
                 const float* __restrict__ state_flow, const float* __restrict__ inj,
                 __half* __restrict__ hhi, __half* __restrict__ hlo) {
    __shared__ __align__(8) float h[SQ];
    __shared__ __align__(8) unsigned long long part[512];
    const int tid = threadIdx.x;
    const int s = tid & 127;
    const int q = tid >> 7;          // 0..3
    const int b = blockIdx.x;

    unsigned long long wv[32];
    #pragma unroll
    for (int j = 0; j < 32; ++j) {
        int k = q * 32 + j;
        wv[j] = pk2(gate_w[s * SQ + k], state_flow[s * SQ + k]);
    }
    float gb = (q == 0) ? gate_b[s] : 0.0f;
    if (q == 0) h[s] = 0.0f;
    __syncthreads();

    const float* injb = inj + (size_t)b * TQ * SQ;
    for (int t = 0; t < TQ; ++t) {
        float injv = (q == 0) ? injb[(size_t)t * SQ + s] : 0.0f;
        unsigned long long acc2 = 0ull;
        const float2* h2 = reinterpret_cast<const float2*>(h + q * 32);
        #pragma unroll
        for (int j = 0; j < 16; ++j) {
            float2 hp = h2[j];
            fma2(acc2, pk2(hp.x, hp.x), wv[2 * j]);
            fma2(acc2, pk2(hp.y, hp.y), wv[2 * j + 1]);
        }
        part[tid] = acc2;
        __syncthreads();
        if (q == 0) {
            float2 p0 = *reinterpret_cast<float2*>(&part[s]);
            float2 p1 = *reinterpret_cast<float2*>(&part[s + 128]);
            float2 p2 = *reinterpret_cast<float2*>(&part[s + 256]);
            float2 p3 = *reinterpret_cast<float2*>(&part[s + 384]);
            float accg = p0.x + p1.x + p2.x + p3.x + gb + injv;
            float accf = p0.y + p1.y + p2.y + p3.y;
            float hold = h[s];
            float g = 1.0f / (1.0f + expf(-accg));
            float hn = (1.0f - g) * hold + g * accf;
            h[s] = hn;
            size_t off = ((size_t)(b << 10) + t) * SQ + s;
            __half hh = __float2half_rn(hn);
            hhi[off] = hh;
            hlo[off] = __float2half_rn(hn - __half2float(hh));
        }
        __syncthreads();
    }
}

// ---- narrow HMMA GEMM (128x128, 3-term, for inj) ----
#define ROWP 40
#define MATB (128 * ROWP * 2)
#define NGSM 122880

__global__ __launch_bounds__(256, 1)
void gemm_inj(const __half* __restrict__ Ahi, const __half* __restrict__ Alo,
              const __half* __restrict__ Bhi, const __half* __restrict__ Blo,
              float* __restrict__ outf, int K, int N) {
    constexpr int NSTG = 3;
    constexpr int STGB = 4 * MATB;
    extern __shared__ __align__(16) unsigned char dsm[];
    const uint32_t sbase = smem_u32(dsm);
    const int tid = threadIdx.x, lane = tid & 31, wid = tid >> 5;
    const size_t mBase = (size_t)blockIdx.y * 128, nBase = (size_t)blockIdx.x * 128;

    const int lrow = tid >> 1, lchunk = (tid & 1) * 2;
    const size_t aoff = (mBase + lrow) * (size_t)K + lchunk * 8;
    const size_t boff = (nBase + lrow) * (size_t)K + lchunk * 8;
    const uint32_t soff = (uint32_t)(lrow * 80 + lchunk * 16);
    const int ktiles = K / 32;

    auto issue = [&](int st, int kt) {
        uint32_t sb = sbase + (uint32_t)st * STGB;
        size_t k0 = (size_t)kt * 32;
        const __half* pa = Ahi + aoff + k0;
        const __half* pb = Alo + aoff + k0;
        const __half* pc = Bhi + boff + k0;
        const __half* pd = Blo + boff + k0;
        cpa16(sb + soff,            pa);  cpa16(sb + soff + 16,            pa + 8);
        cpa16(sb + MATB + soff,     pb);  cpa16(sb + MATB + soff + 16,     pb + 8);
        cpa16(sb + 2 * MATB + soff, pc);  cpa16(sb + 2 * MATB + soff + 16, pc + 8);
        cpa16(sb + 3 * MATB + soff, pd);  cpa16(sb + 3 * MATB + soff + 16, pd + 8);
        asm volatile("cp.async.commit_group;" ::: "memory");
    };
    for (int s = 0; s < 2; ++s) issue(s, s);

    const int wy = wid >> 2, wx = wid & 3;
    const int m_w = wy * 64, n_w = wx * 32;
    float acc[4][4][4];
    #pragma unroll
    for (int i = 0; i < 4; ++i)
        #pragma unroll
        for (int j = 0; j < 4; ++j)
            #pragma unroll
            for (int e = 0; e < 4; ++e) acc[i][j][e] = 0.0f;

    for (int kt = 0; kt < ktiles; ++kt) {
        if (ktiles - 1 - kt >= 1) wgrp<1>(); else wgrp<0>();
        __syncthreads();
        if (kt + 2 < ktiles) issue((kt + 2) % NSTG, kt + 2);
        const uint32_t sb = sbase + (uint32_t)(kt % NSTG) * STGB;
        const uint32_t sAh = sb, sAl = sb + MATB, sBh = sb + 2 * MATB, sBl = sb + 3 * MATB;
        #pragma unroll
        for (int kk = 0; kk < 2; ++kk) {
            const int kc = kk * 16;
            const int arow = (lane & 15);
            const int acol = kc + ((lane >> 4) << 3);
            const int brow = (lane & 7) + ((lane >> 4) << 3);
            const int bcol = kc + (lane & 8);
            uint32_t ah[4][4], al[4][4], bh[4][2], bl[4][2];
            #pragma unroll
            for (int mf = 0; mf < 4; ++mf) {
                uint32_t a = (uint32_t)((m_w + mf * 16 + arow) * ROWP + acol) * 2;
                ldsm4(ah[mf][0], ah[mf][1], ah[mf][2], ah[mf][3], sAh + a);
                ldsm4(al[mf][0], al[mf][1], al[mf][2], al[mf][3], sAl + a);
            }
            #pragma unroll
            for (int g = 0; g < 2; ++g) {
                uint32_t a = (uint32_t)((n_w + g * 16 + brow) * ROWP + bcol) * 2;
                uint32_t r0, r1, r2, r3;
                ldsm4(r0, r1, r2, r3, sBh + a);
                bh[g * 2][0] = r0; bh[g * 2][1] = r1; bh[g * 2 + 1][0] = r2; bh[g * 2 + 1][1] = r3;
                ldsm4(r0, r1, r2, r3, sBl + a);
                bl[g * 2][0] = r0; bl[g * 2][1] = r1; bl[g * 2 + 1][0] = r2; bl[g * 2 + 1][1] = r3;
            }
            #pragma unroll
            for (int mf = 0; mf < 4; ++mf)
                #pragma unroll
                for (int nf = 0; nf < 4; ++nf) {
                    mma16816(acc[mf][nf], ah[mf], bh[nf]);
                    mma16816(acc[mf][nf], al[mf], bh[nf]);
                    mma16816(acc[mf][nf], ah[mf], bl[nf]);
                }
        }
        __syncthreads();
    }
    #pragma unroll
    for (int mf = 0; mf < 4; ++mf)
        #pragma unroll
        for (int nf = 0; nf < 4; ++nf) {
            size_t r0 = mBase + m_w + mf * 16 + (lane >> 2);
            size_t cc = nBase + n_w + nf * 8 + (lane & 3) * 2;
            float2 s0 = { acc[mf][nf][0], acc[mf][nf][1] };
            float2 s1 = { acc[mf][nf][2], acc[mf][nf][3] };
            *reinterpret_cast<float2*>(outf + r0 * N + cc) = s0;
            *reinterpret_cast<float2*>(outf + (r0 + 8) * N + cc) = s1;
        }
}

// ---- x2 GEMM (128x256, 2-term A, K=128): + (lnx_hi+lnx_lo), store hi ----
#define W_AB 10240
#define X2SMEM (4 * 4 * W_AB)

__global__ __launch_bounds__(256, 1)
void gemm_x2(const __half* __restrict__ Ahi, const __half* __restrict__ Alo,
             const __half* __restrict__ Bhi,
             const __half* __restrict__ exh, const __half* __restrict__ exl,
             __half* __restrict__ ohi, int K, int N) {
    constexpr int NSTG = 4;
    constexpr int STGB = 4 * W_AB;
    extern __shared__ __align__(16) unsigned char dsm[];
    const uint32_t sbase = smem_u32(dsm);
    const int tid = threadIdx.x, lane = tid & 31, wid = tid >> 5;
    const size_t mBase = (size_t)blockIdx.y * 128, nBase = (size_t)blockIdx.x * 256;

    const int lrow = tid >> 1, lchunk = (tid & 1) * 2;
    const size_t aoff  = (mBase + lrow) * (size_t)K + lchunk * 8;
    const size_t boff0 = (nBase + lrow) * (size_t)K + lchunk * 8;
    const size_t boff1 = (nBase + lrow + 128) * (size_t)K + lchunk * 8;
    const uint32_t soff  = (uint32_t)(lrow * 80 + lchunk * 16);
    const uint32_t soff1 = (uint32_t)((lrow + 128) * 80 + lchunk * 16);
    const int ktiles = K / 32;

    auto issue = [&](int st, int kt) {
        uint32_t sb = sbase + (uint32_t)st * STGB;
        size_t k0 = (size_t)kt * 32;
        const __half* pa = Ahi + aoff + k0;
        const __half* pb = Alo + aoff + k0;
        const __half* pc = Bhi + boff0 + k0;
        const __half* pd = Bhi + boff1 + k0;
        cpa16(sb + soff,            pa);  cpa16(sb + soff + 16,            pa + 8);
        cpa16(sb + W_AB + soff,     pb);  cpa16(sb + W_AB + soff + 16,     pb + 8);
        cpa16(sb + 2 * W_AB + soff, pc);  cpa16(sb + 2 * W_AB + soff + 16, pc + 8);
        cpa16(sb + 2 * W_AB + soff1, pd); cpa16(sb + 2 * W_AB + soff1 + 16, pd + 8);
        asm volatile("cp.async.commit_group;" ::: "memory");
    };
    const int npre = ktiles < 3 ? ktiles : 3;
    for (int s = 0; s < npre; ++s) issue(s, s);

    const int wy = wid >> 2, wx = wid & 3;
    const int m_w = wy * 64, n_w = wx * 64;

    float acc[4][8][4];
    #pragma unroll
    for (int i = 0; i < 4; ++i)
        #pragma unroll
        for (int j = 0; j < 8; ++j)
            #pragma unroll
            for (int e = 0; e < 4; ++e) acc[i][j][e] = 0.0f;

    for (int kt = 0; kt < ktiles; ++kt) {
        const int rem = ktiles - 1 - kt;
        if (rem >= 2) wgrp<2>(); else if (rem == 1) wgrp<1>(); else wgrp<0>();
        __syncthreads();
        if (kt + 3 < ktiles) issue((kt + 3) % NSTG, kt + 3);

        const uint32_t sb = sbase + (uint32_t)(kt % NSTG) * STGB;
        const uint32_t sAh = sb, sAl = sb + W_AB, sBh = sb + 2 * W_AB;

        #pragma unroll
        for (int kk = 0; kk < 2; ++kk) {
            const int kc = kk * 16;
            const int arow = (lane & 15);
            const int acol = kc + ((lane >> 4) << 3);
            const int brow = (lane & 7) + ((lane >> 4) << 3);
            const int bcol = kc + (lane & 8);
            uint32_t ah[4][4], al[4][4], bh[8][2];
            #pragma unroll
            for (int mf = 0; mf < 4; ++mf) {
                uint32_t a = (uint32_t)((m_w + mf * 16 + arow) * ROWP + acol) * 2;
                ldsm4(ah[mf][0], ah[mf][1], ah[mf][2], ah[mf][3], sAh + a);
                ldsm4(al[mf][0], al[mf][1], al[mf][2], al[mf][3], sAl + a);
            }
            #pragma unroll
            for (int g = 0; g < 4; ++g) {
                uint32_t a = (uint32_t)((n_w + g * 16 + brow) * ROWP + bcol) * 2;
                uint32_t r0, r1, r2, r3;
                ldsm4(r0, r1, r2, r3, sBh + a);
                bh[g * 2][0] = r0; bh[g * 2][1] = r1; bh[g * 2 + 1][0] = r2; bh[g * 2 + 1][1] = r3;
            }
            #pragma unroll
            for (int mf = 0; mf < 4; ++mf)
                #pragma unroll
                for (int nf = 0; nf < 8; ++nf) {
                    mma16816(acc[mf][nf], ah[mf], bh[nf]);
                    mma16816(acc[mf][nf], al[mf], bh[nf]);
                }
        }
        __syncthreads();
    }

    #pragma unroll
    for (int mf = 0; mf < 4; ++mf) {
        #pragma unroll
        for (int nf = 0; nf < 8; ++nf) {
            size_t r0 = mBase + m_w + mf * 16 + (lane >> 2);
            size_t cc = nBase + n_w + nf * 8 + (lane & 3) * 2;
            float2 e0h = unpkh2(*reinterpret_cast<const uint32_t*>(exh + r0 * N + cc));
            float2 e0l = unpkh2(*reinterpret_cast<const uint32_t*>(exl + r0 * N + cc));
            float2 e1h = unpkh2(*reinterpret_cast<const uint32_t*>(exh + (r0 + 8) * N + cc));
            float2 e1l = unpkh2(*reinterpret_cast<const uint32_t*>(exl + (r0 + 8) * N + cc));
            float v0 = acc[mf][nf][0] + e0h.x + e0l.x;
            float v1 = acc[mf][nf][1] + e0h.y + e0l.y;
            float v2 = acc[mf][nf][2] + e1h.x + e1l.x;
            float v3 = acc[mf][nf][3] + e1h.y + e1l.y;
            *reinterpret_cast<uint32_t*>(ohi + r0 * N + cc) = pkh2(v0, v1);
            *reinterpret_cast<uint32_t*>(ohi + (r0 + 8) * N + cc) = pkh2(v2, v3);
        }
    }
}

// ---- 1-term HMMA GEMM (128x128 tile, 3 stages, 2 CTAs/SM) ----
// EPI: 2 = +bias gelu store hi, 3 = +bias fp32 store
#define G1_STG (2 * W_AB)
#define G1_SMEM (3 * G1_STG)   // 61440

template <int EPI>
__global__ __launch_bounds__(256, 2)
void gemm1(const __half* __restrict__ A, const __half* __restrict__ B,
           const float* __restrict__ ext, float* __restrict__ outf,
           __half* __restrict__ ohi, int K, int N) {
    constexpr int NSTG = 3;
    extern __shared__ __align__(16) unsigned char dsm[];
    const uint32_t sbase = smem_u32(dsm);
    const int tid = threadIdx.x, lane = tid & 31, wid = tid >> 5;
    const size_t mBase = (size_t)blockIdx.y * 128, nBase = (size_t)blockIdx.x * 128;

    const int lrow = tid >> 1, lchunk = (tid & 1) * 2;
    const size_t aoff = (mBase + lrow) * (size_t)K + lchunk * 8;
    const size_t boff = (nBase + lrow) * (size_t)K + lchunk * 8;
    const uint32_t soff = (uint32_t)(lrow * 80 + lchunk * 16);
    const int ktiles = K / 32;

    auto issue = [&](int st, int kt) {
        uint32_t sb = sbase + (uint32_t)st * G1_STG;
        size_t k0 = (size_t)kt * 32;
        const __half* pa = A + aoff + k0;
        const __half* pb = B + boff + k0;
        cpa16(sb + soff,        pa);  cpa16(sb + soff + 16,        pa + 8);
        cpa16(sb + W_AB + soff, pb);  cpa16(sb + W_AB + soff + 16, pb + 8);
        asm volatile("cp.async.commit_group;" ::: "memory");
    };
    for (int s = 0; s < 2; ++s) issue(s, s);

    const int wy = wid >> 2, wx = wid & 3;
    const int m_w = wy * 64, n_w = wx * 32;

    float acc[4][4][4];
    #pragma unroll
    for (int i = 0; i < 4; ++i)
        #pragma unroll
        for (int j = 0; j < 4; ++j)
            #pragma unroll
            for (int e = 0; e < 4; ++e) acc[i][j][e] = 0.0f;

    for (int kt = 0; kt < ktiles; ++kt) {
        if (ktiles - 1 - kt >= 1) wgrp<1>(); else wgrp<0>();
        __syncthreads();
        if (kt + 2 < ktiles) issue((kt + 2) % NSTG, kt + 2);

        const uint32_t sb = sbase + (uint32_t)(kt % NSTG) * G1_STG;
        const uint32_t sA = sb, sB = sb + W_AB;

        #pragma unroll
        for (int kk = 0; kk < 2; ++kk) {
            const int kc = kk * 16;
            const int arow = (lane & 15);
            const int acol = kc + ((lane >> 4) << 3);
            const int brow = (lane & 7) + ((lane >> 4) << 3);
            const int bcol = kc + (lane & 8);
            uint32_t ah[4][4], bh[4][2];
            #pragma unroll
            for (int mf = 0; mf < 4; ++mf) {
                uint32_t a = (uint32_t)((m_w + mf * 16 + arow) * ROWP + acol) * 2;
                ldsm4(ah[mf][0], ah[mf][1], ah[mf][2], ah[mf][3], sA + a);
            }
            #pragma unroll
            for (int g = 0; g < 2; ++g) {
                uint32_t a = (uint32_t)((n_w + g * 16 + brow) * ROWP + bcol) * 2;
                uint32_t r0, r1, r2, r3;
                ldsm4(r0, r1, r2, r3, sB + a);
                bh[g * 2][0] = r0; bh[g * 2][1] = r1; bh[g * 2 + 1][0] = r2; bh[g * 2 + 1][1] = r3;
            }
            #pragma unroll
            for (int mf = 0; mf < 4; ++mf)
                #pragma unroll
                for (int nf = 0; nf < 4; ++nf)
                    mma16816(acc[mf][nf], ah[mf], bh[nf]);
        }
        __syncthreads();
    }

    #pragma unroll
    for (int mf = 0; mf < 4; ++mf) {
        #pragma unroll
        for (int nf = 0; nf < 4; ++nf) {
            size_t r0 = mBase + m_w + mf * 16 + (lane >> 2);
            size_t cc = nBase + n_w + nf * 8 + (lane & 3) * 2;
            float2 bb = *reinterpret_cast<const float2*>(ext + cc);
            float v0 = acc[mf][nf][0] + bb.x, v1 = acc[mf][nf][1] + bb.y;
            float v2 = acc[mf][nf][2] + bb.x, v3 = acc[mf][nf][3] + bb.y;
            if (EPI == 2) {
                v0 = gelu_exact(v0); v1 = gelu_exact(v1);
                v2 = gelu_exact(v2); v3 = gelu_exact(v3);
                *reinterpret_cast<uint32_t*>(ohi + r0 * N + cc) = pkh2(v0, v1);
                *reinterpret_cast<uint32_t*>(ohi + (r0 + 8) * N + cc) = pkh2(v2, v3);
            } else {
                float2 s0 = { v0, v1 }, s1 = { v2, v3 };
                *reinterpret_cast<float2*>(outf + r0 * N + cc) = s0;
                *reinterpret_cast<float2*>(outf + (r0 + 8) * N + cc) = s1;
            }
        }
    }
}

// ---- launch ----
extern "C" void kernel_launch(void* const* d_in, const int* in_sizes, int n_in,
                              void* d_out, int out_size) {
    const float* x          = (const float*)d_in[0];
    const float* ln1_w      = (const float*)d_in[1];
    const float* ln1_b      = (const float*)d_in[2];
    const float* state_flow = (const float*)d_in[3];
    const float* injection  = (const float*)d_in[4];
    const float* readout    = (const float*)d_in[5];
    const float* gate_w     = (const float*)d_in[6];
    const float* gate_b     = (const float*)d_in[7];
    const float* w1         = (const float*)d_in[8];
    const float* b1         = (const float*)d_in[9];
    const float* w2         = (const float*)d_in[10];
    const float* b2         = (const float*)d_in[11];
    const float* ln2_w      = (const float*)d_in[12];
    const float* ln2_b      = (const float*)d_in[13];
    float* out = (float*)d_out;

    float *inj, *x3;
    __half *lnxh, *lnxl, *hh, *hl, *x2h, *hbh;
    __half *wih, *wil, *roh, *w1h, *w2h;
    cudaGetSymbolAddress((void**)&lnxh, g_lnx_hi);
    cudaGetSymbolAddress((void**)&lnxl, g_lnx_lo);
    cudaGetSymbolAddress((void**)&inj, g_inj);
    cudaGetSymbolAddress((void**)&hh, g_h_hi);
    cudaGetSymbolAddress((void**)&hl, g_h_lo);
    cudaGetSymbolAddress((void**)&x2h, g_x2_hi);
    cudaGetSymbolAddress((void**)&hbh, g_hb_hi);
    cudaGetSymbolAddress((void**)&x3, g_x3);
    cudaGetSymbolAddress((void**)&wih, g_wi_hi);
    cudaGetSymbolAddress((void**)&wil, g_wi_lo);
    cudaGetSymbolAddress((void**)&roh, g_ro_hi);
    cudaGetSymbolAddress((void**)&w1h, g_w1_hi);
    cudaGetSymbolAddress((void**)&w2h, g_w2_hi);

    cudaFuncSetAttribute(gemm_inj, cudaFuncAttributeMaxDynamicSharedMemorySize, NGSM);
    cudaFuncSetAttribute(gemm_x2,  cudaFuncAttributeMaxDynamicSharedMemorySize, X2SMEM);
    cudaFuncSetAttribute(gemm1<2>, cudaFuncAttributeMaxDynamicSharedMemorySize, G1_SMEM);
    cudaFuncSetAttribute(gemm1<3>, cudaFuncAttributeMaxDynamicSharedMemorySize, G1_SMEM);

    // weight conversions
    conv_split<<<(SQ * DQ / 8) / 256, 256>>>(injection, wih, wil);
    conv_hi<<<(DQ * SQ / 8) / 256, 256>>>(readout, roh);
    conv_hi<<<(int)(((size_t)HQ * DQ / 8) / 256), 256>>>(w1, w1h);
    conv_hi<<<(int)(((size_t)DQ * HQ / 8) / 256), 256>>>(w2, w2h);
    // LN1 -> hi/lo only (no fp32 copy)
    ln_kernel<false, true, false><<<MQ, 256>>>(x, ln1_w, ln1_b, nullptr, lnxh, lnxl);
    // inj = lnx @ injection^T   [M x 128], K=1024  (3-term)
    gemm_inj<<<dim3(1, MQ / 128), 256, NGSM>>>(lnxh, lnxl, wih, wil, inj, DQ, SQ);
    // scan -> h hi/lo
    scan_kernel<<<BQ, 512>>>(gate_w, gate_b, state_flow, inj, hh, hl);
    // x2 = (lnx_hi+lnx_lo) + h @ readout^T  (2-term A, hi-only store)
    gemm_x2<<<dim3(DQ / 256, MQ / 128), 256, X2SMEM>>>(hh, hl, roh, lnxh, lnxl, x2h, SQ, DQ);
    // hb = gelu(x2 @ w1^T + b1)  (1-term, 2 CTA/SM)
    gemm1<2><<<dim3(HQ / 128, MQ / 128), 256, G1_SMEM>>>(x2h, w1h, b1, nullptr, hbh, DQ, HQ);
    // x3 = hb @ w2^T + b2        (1-term, 2 CTA/SM, fp32 store)
    gemm1<3><<<dim3(DQ / 128, MQ / 128), 256, G1_SMEM>>>(hbh, w2h, b2, x3, nullptr, HQ, DQ);
    // out = x3 + LN(x3)
    ln_kernel<true, false, true><<<MQ, 256>>>(x3, ln2_w, ln2_b, out, nullptr, nullptr);
}